// round 3
// baseline (speedup 1.0000x reference)
#include <cuda_runtime.h>
#include <math.h>

// Problem shape (fixed by the dataset)
#define BB 8
#define NN 4096
#define MM 4096
#define CC 128

#define TILE 128
#define KC   32    // k-slice per stage (4 stages)
#define RS   33    // smem row stride (floats): odd -> conflict-free

// Scratch (no allocations allowed in kernel_launch)
__device__ float g_rowmin[BB * NN];
__device__ float g_colmin[BB * MM];
__device__ float g_x2[BB * NN];
__device__ float g_y2[BB * MM];

__global__ void init_mins_kernel() {
    int i = blockIdx.x * blockDim.x + threadIdx.x;
    if (i < BB * NN) g_rowmin[i] = __int_as_float(0x7F800000);
    if (i < BB * MM) g_colmin[i] = __int_as_float(0x7F800000);
}

// One warp per point: squared L2 norm of each 128-dim row.
__global__ void norms_kernel(const float* __restrict__ X, const float* __restrict__ Y) {
    int gwarp = (blockIdx.x * blockDim.x + threadIdx.x) >> 5;
    int lane = threadIdx.x & 31;
    const float* src = blockIdx.y ? Y : X;
    float* dst = blockIdx.y ? g_y2 : g_x2;
    if (gwarp >= BB * NN) return;
    const float* row = src + (size_t)gwarp * CC;
    float s = 0.0f;
#pragma unroll
    for (int q = 0; q < 4; q++) {
        float v = row[lane + 32 * q];
        s += v * v;
    }
#pragma unroll
    for (int off = 16; off > 0; off >>= 1)
        s += __shfl_xor_sync(0xFFFFFFFFu, s, off);
    if (lane == 0) dst[gwarp] = s;
}

// Fused distance-tile + min-reduction kernel.
// Grid: (MM/TILE, NN/TILE, BB), 256 threads.
// SMEM: 2 * TILE * RS * 4 = 33,792 bytes (static, under 48KB).
// Layout: As[row][k], row 0..127, k 0..31, stride RS=33.
__global__ void __launch_bounds__(256, 2)
chamfer_tile_kernel(const float* __restrict__ X, const float* __restrict__ Y) {
    __shared__ float As[TILE * RS];   // [row][k]
    __shared__ float Bs[TILE * RS];   // [row][k]

    const int b  = blockIdx.z;
    const int n0 = blockIdx.y * TILE;
    const int m0 = blockIdx.x * TILE;

    const float* xb = X + ((size_t)b * NN + n0) * CC;
    const float* yb = Y + ((size_t)b * MM + m0) * CC;

    const int tid  = threadIdx.x;
    const int lane = tid & 31;
    const int w    = tid >> 5;        // 0..7

    const int tx = tid & 15;          // col group
    const int ty = tid >> 4;          // row group

    float acc[8][8];
#pragma unroll
    for (int i = 0; i < 8; i++)
#pragma unroll
        for (int j = 0; j < 8; j++)
            acc[i][j] = 0.0f;

    // Four k-stages of KC=32 channels each.
#pragma unroll
    for (int s = 0; s < 4; s++) {
        // Stage: load KC channels of both tiles ([row][k] layout, no transpose).
        // Coalesced global reads (warp reads 32 consecutive c), conflict-free
        // smem stores (consecutive lanes -> consecutive addresses).
#pragma unroll 4
        for (int p = 0; p < 16; p++) {
            int row = p * 8 + w;          // 0..127
            As[row * RS + lane] = xb[(size_t)row * CC + s * KC + lane];
            Bs[row * RS + lane] = yb[(size_t)row * CC + s * KC + lane];
        }
        __syncthreads();

        // Main loop: rows = ty + 16*i, cols = tx + 16*j.
        // a-frag: 2 addresses/warp (broadcast). b-frag: banks (tx+k) mod 32,
        // 16 distinct + pairwise broadcast -> conflict-free.
#pragma unroll 8
        for (int k = 0; k < KC; k++) {
            float a[8], bf[8];
#pragma unroll
            for (int i = 0; i < 8; i++) a[i]  = As[(ty + 16 * i) * RS + k];
#pragma unroll
            for (int j = 0; j < 8; j++) bf[j] = Bs[(tx + 16 * j) * RS + k];
#pragma unroll
            for (int i = 0; i < 8; i++)
#pragma unroll
                for (int j = 0; j < 8; j++)
                    acc[i][j] += a[i] * bf[j];
        }
        __syncthreads();   // readers done before restage / scratch reuse
    }

    // Epilogue: d2 = x2 + y2 - 2*dot, clamp, then row/col mins.
    float x2r[8], y2c[8];
#pragma unroll
    for (int i = 0; i < 8; i++) x2r[i] = g_x2[(size_t)b * NN + n0 + ty + 16 * i];
#pragma unroll
    for (int j = 0; j < 8; j++) y2c[j] = g_y2[(size_t)b * MM + m0 + tx + 16 * j];

    float rmin[8], cmin[8];
#pragma unroll
    for (int i = 0; i < 8; i++) rmin[i] = __int_as_float(0x7F800000);
#pragma unroll
    for (int j = 0; j < 8; j++) cmin[j] = __int_as_float(0x7F800000);

#pragma unroll
    for (int i = 0; i < 8; i++) {
#pragma unroll
        for (int j = 0; j < 8; j++) {
            float d2 = fmaxf(x2r[i] + y2c[j] - 2.0f * acc[i][j], 0.0f);
            rmin[i] = fminf(rmin[i], d2);
            cmin[j] = fminf(cmin[j], d2);
        }
    }

    // Block-level reduction (reuse As as scratch: 128 x 16 floats = 2048 < 4224)
    float* red = As;

    // Row mins: red[row][tx]
#pragma unroll
    for (int i = 0; i < 8; i++) red[(ty + 16 * i) * 16 + tx] = rmin[i];
    __syncthreads();
    if (tid < 128) {
        float v = red[tid * 16];
#pragma unroll
        for (int t = 1; t < 16; t++) v = fminf(v, red[tid * 16 + t]);
        atomicMin((int*)&g_rowmin[(size_t)b * NN + n0 + tid], __float_as_int(v));
    }
    __syncthreads();

    // Col mins: red[col][ty]
#pragma unroll
    for (int j = 0; j < 8; j++) red[(tx + 16 * j) * 16 + ty] = cmin[j];
    __syncthreads();
    if (tid < 128) {
        float v = red[tid * 16];
#pragma unroll
        for (int t = 1; t < 16; t++) v = fminf(v, red[tid * 16 + t]);
        atomicMin((int*)&g_colmin[(size_t)b * MM + m0 + tid], __float_as_int(v));
    }
}

// Single-block weighted reduction.
__global__ void finalize_kernel(const float* __restrict__ w1,
                                const float* __restrict__ w2,
                                float* __restrict__ out) {
    __shared__ double sh[256];
    int tid = threadIdx.x;
    double s = 0.0;
    for (int i = tid; i < BB * NN; i += 256)
        s += (double)w1[i] * sqrtf(g_rowmin[i]);
    for (int i = tid; i < BB * MM; i += 256)
        s += (double)w2[i] * sqrtf(g_colmin[i]);
    sh[tid] = s;
    __syncthreads();
    for (int off = 128; off > 0; off >>= 1) {
        if (tid < off) sh[tid] += sh[tid + off];
        __syncthreads();
    }
    if (tid == 0) out[0] = (float)(sh[0] * 0.5);
}

extern "C" void kernel_launch(void* const* d_in, const int* in_sizes, int n_in,
                              void* d_out, int out_size) {
    const float* set1 = (const float*)d_in[0];
    const float* set2 = (const float*)d_in[1];
    const float* w1   = (const float*)d_in[2];
    const float* w2   = (const float*)d_in[3];
    float* out = (float*)d_out;

    // Reset global min buffers
    init_mins_kernel<<<(BB * NN + 255) / 256, 256>>>();

    // Squared norms: one warp per point, grid.y selects X/Y
    dim3 ngrid((BB * NN) / 8, 2, 1);
    norms_kernel<<<ngrid, 256>>>(set1, set2);

    // Main fused tile kernel
    dim3 tgrid(MM / TILE, NN / TILE, BB);
    chamfer_tile_kernel<<<tgrid, 256>>>(set1, set2);

    // Weighted sum -> scalar
    finalize_kernel<<<1, 256>>>(w1, w2, out);
}

// round 4
// speedup vs baseline: 2.9427x; 2.9427x over previous
#include <cuda_runtime.h>
#include <math.h>

// Problem shape (fixed by the dataset)
#define BB 8
#define NN 4096
#define MM 4096
#define CC 128

#define TILE 128
#define KC   32    // k-slice per stage (4 stages)
#define RS   36    // smem row stride (words): (4g+t) mod 32 distinct -> conflict-free

// Scratch (no allocations allowed in kernel_launch)
__device__ float  g_rowmin[BB * NN];
__device__ float  g_colmin[BB * MM];
__device__ float  g_x2[BB * NN];
__device__ float  g_y2[BB * MM];
__device__ double g_acc;

__global__ void init_mins_kernel() {
    int i = blockIdx.x * blockDim.x + threadIdx.x;
    if (i < BB * NN) g_rowmin[i] = __int_as_float(0x7F800000);
    if (i < BB * MM) g_colmin[i] = __int_as_float(0x7F800000);
    if (i == 0) g_acc = 0.0;
}

// One warp per point: squared L2 norm of each 128-dim row.
__global__ void norms_kernel(const float* __restrict__ X, const float* __restrict__ Y) {
    int gwarp = (blockIdx.x * blockDim.x + threadIdx.x) >> 5;
    int lane = threadIdx.x & 31;
    const float* src = blockIdx.y ? Y : X;
    float* dst = blockIdx.y ? g_y2 : g_x2;
    if (gwarp >= BB * NN) return;
    const float* row = src + (size_t)gwarp * CC;
    float s = 0.0f;
#pragma unroll
    for (int q = 0; q < 4; q++) {
        float v = row[lane + 32 * q];
        s += v * v;
    }
#pragma unroll
    for (int off = 16; off > 0; off >>= 1)
        s += __shfl_xor_sync(0xFFFFFFFFu, s, off);
    if (lane == 0) dst[gwarp] = s;
}

__device__ __forceinline__ unsigned f2tf32(float x) {
    unsigned r;
    asm("cvt.rna.tf32.f32 %0, %1;" : "=r"(r) : "f"(x));
    return r;
}

__device__ __forceinline__ void mma_tf32(float& c0, float& c1, float& c2, float& c3,
                                         unsigned a0, unsigned a1, unsigned a2, unsigned a3,
                                         unsigned b0, unsigned b1) {
    asm volatile(
        "mma.sync.aligned.m16n8k8.row.col.f32.tf32.tf32.f32 "
        "{%0,%1,%2,%3}, {%4,%5,%6,%7}, {%8,%9}, {%0,%1,%2,%3};"
        : "+f"(c0), "+f"(c1), "+f"(c2), "+f"(c3)
        : "r"(a0), "r"(a1), "r"(a2), "r"(a3), "r"(b0), "r"(b1));
}

// Fused distance-tile + min-reduction kernel (tf32 tensor cores).
// Grid: (MM/TILE, NN/TILE, BB), 256 threads = 8 warps.
// Warp layout: wn = wid>>2 (2 row-halves of 64), wm = wid&3 (4 col-quarters of 32).
// Each warp: 64x32 tile = 4 m16-tiles x 4 n8-tiles of m16n8k8.
__global__ void __launch_bounds__(256, 2)
chamfer_tile_kernel(const float* __restrict__ X, const float* __restrict__ Y) {
    __shared__ unsigned As[TILE * RS];   // [row][k], tf32 bits
    __shared__ unsigned Bs[TILE * RS];

    const int b  = blockIdx.z;
    const int n0 = blockIdx.y * TILE;
    const int m0 = blockIdx.x * TILE;

    const float* xb = X + ((size_t)b * NN + n0) * CC;
    const float* yb = Y + ((size_t)b * MM + m0) * CC;

    const int tid  = threadIdx.x;
    const int lane = tid & 31;
    const int w    = tid >> 5;        // 0..7
    const int g    = lane >> 2;       // groupID 0..7
    const int t    = lane & 3;        // threadID-in-group 0..3
    const int wn   = w >> 2;          // 0..1 -> row offset wn*64
    const int wm   = w & 3;           // 0..3 -> col offset wm*32

    float acc[4][4][4];               // [mt][nt][c0..c3]
#pragma unroll
    for (int mt = 0; mt < 4; mt++)
#pragma unroll
        for (int nt = 0; nt < 4; nt++)
#pragma unroll
            for (int c = 0; c < 4; c++)
                acc[mt][nt][c] = 0.0f;

    // Four k-stages of KC=32 channels.
#pragma unroll
    for (int s = 0; s < 4; s++) {
        // Stage: coalesced global reads, conflict-free smem stores, cvt to tf32 once.
#pragma unroll 4
        for (int p = 0; p < 16; p++) {
            int row = p * 8 + w;
            As[row * RS + lane] = f2tf32(xb[(size_t)row * CC + s * KC + lane]);
            Bs[row * RS + lane] = f2tf32(yb[(size_t)row * CC + s * KC + lane]);
        }
        __syncthreads();

#pragma unroll
        for (int ks = 0; ks < 4; ks++) {
            const int k0 = ks * 8;
            unsigned a[4][4], bf[4][2];
#pragma unroll
            for (int mt = 0; mt < 4; mt++) {
                int rb = (wn * 64 + mt * 16 + g) * RS + k0;
                a[mt][0] = As[rb + t];
                a[mt][1] = As[rb + 8 * RS + t];
                a[mt][2] = As[rb + t + 4];
                a[mt][3] = As[rb + 8 * RS + t + 4];
            }
#pragma unroll
            for (int nt = 0; nt < 4; nt++) {
                int cb = (wm * 32 + nt * 8 + g) * RS + k0;
                bf[nt][0] = Bs[cb + t];
                bf[nt][1] = Bs[cb + t + 4];
            }
#pragma unroll
            for (int mt = 0; mt < 4; mt++)
#pragma unroll
                for (int nt = 0; nt < 4; nt++)
                    mma_tf32(acc[mt][nt][0], acc[mt][nt][1], acc[mt][nt][2], acc[mt][nt][3],
                             a[mt][0], a[mt][1], a[mt][2], a[mt][3],
                             bf[nt][0], bf[nt][1]);
        }
        __syncthreads();
    }

    // Epilogue. C fragment mapping (m16n8k8): c0=(g,2t) c1=(g,2t+1) c2=(g+8,2t) c3=(g+8,2t+1).
    float y2a[4], y2b[4];
#pragma unroll
    for (int nt = 0; nt < 4; nt++) {
        int c0 = m0 + wm * 32 + nt * 8 + 2 * t;
        y2a[nt] = g_y2[(size_t)b * MM + c0];
        y2b[nt] = g_y2[(size_t)b * MM + c0 + 1];
    }

    float rmin0[4], rmin1[4];                     // per mt (rows g, g+8)
    float cmin0[4], cmin1[4];                     // per nt (cols 2t, 2t+1), min over all mt
#pragma unroll
    for (int q = 0; q < 4; q++) {
        cmin0[q] = __int_as_float(0x7F800000);
        cmin1[q] = __int_as_float(0x7F800000);
    }

#pragma unroll
    for (int mt = 0; mt < 4; mt++) {
        int r0 = n0 + wn * 64 + mt * 16 + g;
        float x2a = g_x2[(size_t)b * NN + r0];
        float x2b = g_x2[(size_t)b * NN + r0 + 8];
        float ra = __int_as_float(0x7F800000), rb = ra;
#pragma unroll
        for (int nt = 0; nt < 4; nt++) {
            float d00 = fmaxf(x2a + y2a[nt] - 2.0f * acc[mt][nt][0], 0.0f);
            float d01 = fmaxf(x2a + y2b[nt] - 2.0f * acc[mt][nt][1], 0.0f);
            float d10 = fmaxf(x2b + y2a[nt] - 2.0f * acc[mt][nt][2], 0.0f);
            float d11 = fmaxf(x2b + y2b[nt] - 2.0f * acc[mt][nt][3], 0.0f);
            ra = fminf(ra, fminf(d00, d01));
            rb = fminf(rb, fminf(d10, d11));
            cmin0[nt] = fminf(cmin0[nt], fminf(d00, d10));
            cmin1[nt] = fminf(cmin1[nt], fminf(d01, d11));
        }
        rmin0[mt] = ra;
        rmin1[mt] = rb;
    }

    // Row mins: reduce across t (lanes differing in bits 0,1)
#pragma unroll
    for (int mt = 0; mt < 4; mt++) {
#pragma unroll
        for (int off = 1; off <= 2; off <<= 1) {
            rmin0[mt] = fminf(rmin0[mt], __shfl_xor_sync(0xFFFFFFFFu, rmin0[mt], off));
            rmin1[mt] = fminf(rmin1[mt], __shfl_xor_sync(0xFFFFFFFFu, rmin1[mt], off));
        }
    }
    // Col mins: reduce across g (lanes differing in bits 2,3,4)
#pragma unroll
    for (int nt = 0; nt < 4; nt++) {
#pragma unroll
        for (int off = 4; off <= 16; off <<= 1) {
            cmin0[nt] = fminf(cmin0[nt], __shfl_xor_sync(0xFFFFFFFFu, cmin0[nt], off));
            cmin1[nt] = fminf(cmin1[nt], __shfl_xor_sync(0xFFFFFFFFu, cmin1[nt], off));
        }
    }

    // Cross-warp reduction via smem scratch (reuse As: 512 + 256 words < 4608)
    float* redr = (float*)As;          // [128][4] rowmin per wm
    float* redc = (float*)As + 512;    // [128][2] colmin per wn
    __syncthreads();   // all mainloop smem reads done

    if (t == 0) {
#pragma unroll
        for (int mt = 0; mt < 4; mt++) {
            int r = wn * 64 + mt * 16 + g;
            redr[r * 4 + wm] = rmin0[mt];
            redr[(r + 8) * 4 + wm] = rmin1[mt];
        }
    }
    if (g == 0) {
#pragma unroll
        for (int nt = 0; nt < 4; nt++) {
            int c = wm * 32 + nt * 8 + 2 * t;
            redc[c * 2 + wn] = cmin0[nt];
            redc[(c + 1) * 2 + wn] = cmin1[nt];
        }
    }
    __syncthreads();

    if (tid < 128) {
        float rv = fminf(fminf(redr[tid * 4], redr[tid * 4 + 1]),
                         fminf(redr[tid * 4 + 2], redr[tid * 4 + 3]));
        atomicMin((int*)&g_rowmin[(size_t)b * NN + n0 + tid], __float_as_int(rv));
        float cv = fminf(redc[tid * 2], redc[tid * 2 + 1]);
        atomicMin((int*)&g_colmin[(size_t)b * MM + m0 + tid], __float_as_int(cv));
    }
}

// Multi-block weighted reduction -> atomicAdd into g_acc.
__global__ void partial_final_kernel(const float* __restrict__ w1,
                                     const float* __restrict__ w2) {
    __shared__ double sh[256];
    int tid = threadIdx.x;
    int gid = blockIdx.x * 256 + tid;
    int stride = gridDim.x * 256;
    double s = 0.0;
    for (int i = gid; i < BB * NN; i += stride)
        s += (double)w1[i] * sqrtf(g_rowmin[i]);
    for (int i = gid; i < BB * MM; i += stride)
        s += (double)w2[i] * sqrtf(g_colmin[i]);
    sh[tid] = s;
    __syncthreads();
    for (int off = 128; off > 0; off >>= 1) {
        if (tid < off) sh[tid] += sh[tid + off];
        __syncthreads();
    }
    if (tid == 0) atomicAdd(&g_acc, sh[0]);
}

__global__ void writeout_kernel(float* __restrict__ out) {
    out[0] = (float)(g_acc * 0.5);
}

extern "C" void kernel_launch(void* const* d_in, const int* in_sizes, int n_in,
                              void* d_out, int out_size) {
    const float* set1 = (const float*)d_in[0];
    const float* set2 = (const float*)d_in[1];
    const float* w1   = (const float*)d_in[2];
    const float* w2   = (const float*)d_in[3];
    float* out = (float*)d_out;

    init_mins_kernel<<<(BB * NN + 255) / 256, 256>>>();

    dim3 ngrid((BB * NN) / 8, 2, 1);
    norms_kernel<<<ngrid, 256>>>(set1, set2);

    dim3 tgrid(MM / TILE, NN / TILE, BB);
    chamfer_tile_kernel<<<tgrid, 256>>>(set1, set2);

    partial_final_kernel<<<64, 256>>>(w1, w2);
    writeout_kernel<<<1, 1>>>(out);
}

// round 5
// speedup vs baseline: 3.7027x; 1.2583x over previous
#include <cuda_runtime.h>
#include <math.h>
#include <stdint.h>

// Problem shape (fixed by the dataset)
#define BB 8
#define NN 4096
#define MM 4096
#define CC 128

#define TN 128     // CTA tile rows (set1 points)
#define TM 256     // CTA tile cols (set2 points)
#define KC 32      // k-slice per stage (4 stages)
#define RS 36      // smem row stride (words): conflict-free for frags & stores

#define AW (TN * RS)       // 4608 words
#define BW (TM * RS)       // 9216 words
#define BUFW (AW + BW)     // 13824 words per buffer
#define SMEM_BYTES (2 * BUFW * 4)   // 110,592 B double-buffered

// Scratch (no allocations allowed in kernel_launch)
__device__ float  g_rowmin[BB * NN];
__device__ float  g_colmin[BB * MM];
__device__ float  g_x2[BB * NN];
__device__ float  g_y2[BB * MM];
__device__ double g_acc;

__global__ void init_mins_kernel() {
    int i = blockIdx.x * blockDim.x + threadIdx.x;
    if (i < BB * NN) g_rowmin[i] = __int_as_float(0x7F800000);
    if (i < BB * MM) g_colmin[i] = __int_as_float(0x7F800000);
    if (i == 0) g_acc = 0.0;
}

// One warp per point: squared L2 norm of each 128-dim row.
__global__ void norms_kernel(const float* __restrict__ X, const float* __restrict__ Y) {
    int gwarp = (blockIdx.x * blockDim.x + threadIdx.x) >> 5;
    int lane = threadIdx.x & 31;
    const float* src = blockIdx.y ? Y : X;
    float* dst = blockIdx.y ? g_y2 : g_x2;
    if (gwarp >= BB * NN) return;
    const float* row = src + (size_t)gwarp * CC;
    float s = 0.0f;
#pragma unroll
    for (int q = 0; q < 4; q++) {
        float v = row[lane + 32 * q];
        s += v * v;
    }
#pragma unroll
    for (int off = 16; off > 0; off >>= 1)
        s += __shfl_xor_sync(0xFFFFFFFFu, s, off);
    if (lane == 0) dst[gwarp] = s;
}

__device__ __forceinline__ void cp16(uint32_t saddr, const void* gaddr) {
    asm volatile("cp.async.cg.shared.global [%0], [%1], 16;\n"
                 :: "r"(saddr), "l"(gaddr));
}
__device__ __forceinline__ void cp_commit() {
    asm volatile("cp.async.commit_group;\n");
}
template <int N>
__device__ __forceinline__ void cp_wait() {
    asm volatile("cp.async.wait_group %0;\n" :: "n"(N));
}

__device__ __forceinline__ void mma_tf32(float& c0, float& c1, float& c2, float& c3,
                                         unsigned a0, unsigned a1, unsigned a2, unsigned a3,
                                         unsigned b0, unsigned b1) {
    asm volatile(
        "mma.sync.aligned.m16n8k8.row.col.f32.tf32.tf32.f32 "
        "{%0,%1,%2,%3}, {%4,%5,%6,%7}, {%8,%9}, {%0,%1,%2,%3};"
        : "+f"(c0), "+f"(c1), "+f"(c2), "+f"(c3)
        : "r"(a0), "r"(a1), "r"(a2), "r"(a3), "r"(b0), "r"(b1));
}

// Fused distance-tile + min-reduction kernel (tf32 tensor cores, cp.async pipeline).
// Grid: (MM/TM, NN/TN, BB), 256 threads = 8 warps.
// Warp layout: wn = w>>2 (2 row-halves of 64), wm = w&3 (4 col-slices of 64).
// Each warp: 64x64 tile = 4 m16 x 8 n8 tiles of m16n8k8 tf32.
__global__ void __launch_bounds__(256, 1)
chamfer_tile_kernel(const float* __restrict__ X, const float* __restrict__ Y) {
    extern __shared__ float smem[];

    const int b  = blockIdx.z;
    const int n0 = blockIdx.y * TN;
    const int m0 = blockIdx.x * TM;

    const float* xb = X + ((size_t)b * NN + n0) * CC;
    const float* yb = Y + ((size_t)b * MM + m0) * CC;

    const int tid  = threadIdx.x;
    const int lane = tid & 31;
    const int w    = tid >> 5;        // 0..7
    const int g    = lane >> 2;       // 0..7
    const int t    = lane & 3;        // 0..3
    const int wn   = w >> 2;          // 0..1 -> row offset wn*64
    const int wm   = w & 3;           // 0..3 -> col offset wm*64

    // Staging thread mapping: 32 rows per pass, 16B (4 floats) per thread
    const int sr = tid >> 3;          // 0..31
    const int sc = (tid & 7) * 4;     // 0,4,..,28

    uint32_t sbase = (uint32_t)__cvta_generic_to_shared(smem);

    // Issue cp.async stage s into buffer (s&1)
    auto stage = [&](int s) {
        uint32_t abuf = sbase + ((s & 1) * BUFW) * 4;
        uint32_t bbuf = abuf + AW * 4;
        const float* xs = xb + s * KC;
        const float* ys = yb + s * KC;
#pragma unroll
        for (int p = 0; p < 4; p++) {
            int row = p * 32 + sr;
            cp16(abuf + (row * RS + sc) * 4, xs + (size_t)row * CC + sc);
        }
#pragma unroll
        for (int p = 0; p < 8; p++) {
            int row = p * 32 + sr;
            cp16(bbuf + (row * RS + sc) * 4, ys + (size_t)row * CC + sc);
        }
        cp_commit();
    };

    float acc[4][8][4];
#pragma unroll
    for (int mt = 0; mt < 4; mt++)
#pragma unroll
        for (int nt = 0; nt < 8; nt++)
#pragma unroll
            for (int c = 0; c < 4; c++)
                acc[mt][nt][c] = 0.0f;

    stage(0);

#pragma unroll
    for (int s = 0; s < 4; s++) {
        if (s < 3) stage(s + 1);
        if (s < 3) cp_wait<1>(); else cp_wait<0>();
        __syncthreads();

        const unsigned* As = (const unsigned*)(smem + (s & 1) * BUFW);
        const unsigned* Bs = As + AW;

#pragma unroll
        for (int ks = 0; ks < 4; ks++) {
            const int k0 = ks * 8;
            unsigned a[4][4], bf[8][2];
#pragma unroll
            for (int mt = 0; mt < 4; mt++) {
                int rb = (wn * 64 + mt * 16 + g) * RS + k0;
                a[mt][0] = As[rb + t];
                a[mt][1] = As[rb + 8 * RS + t];
                a[mt][2] = As[rb + t + 4];
                a[mt][3] = As[rb + 8 * RS + t + 4];
            }
#pragma unroll
            for (int nt = 0; nt < 8; nt++) {
                int cb = (wm * 64 + nt * 8 + g) * RS + k0;
                bf[nt][0] = Bs[cb + t];
                bf[nt][1] = Bs[cb + t + 4];
            }
#pragma unroll
            for (int mt = 0; mt < 4; mt++)
#pragma unroll
                for (int nt = 0; nt < 8; nt++)
                    mma_tf32(acc[mt][nt][0], acc[mt][nt][1], acc[mt][nt][2], acc[mt][nt][3],
                             a[mt][0], a[mt][1], a[mt][2], a[mt][3],
                             bf[nt][0], bf[nt][1]);
        }
        __syncthreads();
    }

    // Epilogue. C fragment (m16n8k8): c0=(g,2t) c1=(g,2t+1) c2=(g+8,2t) c3=(g+8,2t+1).
    float y2a[8], y2b[8];
#pragma unroll
    for (int nt = 0; nt < 8; nt++) {
        int c0 = m0 + wm * 64 + nt * 8 + 2 * t;
        y2a[nt] = g_y2[(size_t)b * MM + c0];
        y2b[nt] = g_y2[(size_t)b * MM + c0 + 1];
    }

    float rmin0[4], rmin1[4];
    float cmin0[8], cmin1[8];
#pragma unroll
    for (int q = 0; q < 8; q++) {
        cmin0[q] = __int_as_float(0x7F800000);
        cmin1[q] = __int_as_float(0x7F800000);
    }

#pragma unroll
    for (int mt = 0; mt < 4; mt++) {
        int r0 = n0 + wn * 64 + mt * 16 + g;
        float x2a = g_x2[(size_t)b * NN + r0];
        float x2b = g_x2[(size_t)b * NN + r0 + 8];
        float ra = __int_as_float(0x7F800000), rb = ra;
#pragma unroll
        for (int nt = 0; nt < 8; nt++) {
            float d00 = fmaxf(x2a + y2a[nt] - 2.0f * acc[mt][nt][0], 0.0f);
            float d01 = fmaxf(x2a + y2b[nt] - 2.0f * acc[mt][nt][1], 0.0f);
            float d10 = fmaxf(x2b + y2a[nt] - 2.0f * acc[mt][nt][2], 0.0f);
            float d11 = fmaxf(x2b + y2b[nt] - 2.0f * acc[mt][nt][3], 0.0f);
            ra = fminf(ra, fminf(d00, d01));
            rb = fminf(rb, fminf(d10, d11));
            cmin0[nt] = fminf(cmin0[nt], fminf(d00, d10));
            cmin1[nt] = fminf(cmin1[nt], fminf(d01, d11));
        }
        rmin0[mt] = ra;
        rmin1[mt] = rb;
    }

    // Row mins: reduce across t (lane bits 0,1)
#pragma unroll
    for (int mt = 0; mt < 4; mt++) {
#pragma unroll
        for (int off = 1; off <= 2; off <<= 1) {
            rmin0[mt] = fminf(rmin0[mt], __shfl_xor_sync(0xFFFFFFFFu, rmin0[mt], off));
            rmin1[mt] = fminf(rmin1[mt], __shfl_xor_sync(0xFFFFFFFFu, rmin1[mt], off));
        }
    }
    // Col mins: reduce across g (lane bits 2,3,4)
#pragma unroll
    for (int nt = 0; nt < 8; nt++) {
#pragma unroll
        for (int off = 4; off <= 16; off <<= 1) {
            cmin0[nt] = fminf(cmin0[nt], __shfl_xor_sync(0xFFFFFFFFu, cmin0[nt], off));
            cmin1[nt] = fminf(cmin1[nt], __shfl_xor_sync(0xFFFFFFFFu, cmin1[nt], off));
        }
    }

    // Cross-warp reduction via smem scratch
    float* redr = smem;           // [128][4] rowmin per wm
    float* redc = smem + 512;     // [256][2] colmin per wn

    if (t == 0) {
#pragma unroll
        for (int mt = 0; mt < 4; mt++) {
            int r = wn * 64 + mt * 16 + g;
            redr[r * 4 + wm] = rmin0[mt];
            redr[(r + 8) * 4 + wm] = rmin1[mt];
        }
    }
    if (g == 0) {
#pragma unroll
        for (int nt = 0; nt < 8; nt++) {
            int c = wm * 64 + nt * 8 + 2 * t;
            redc[c * 2 + wn] = cmin0[nt];
            redc[(c + 1) * 2 + wn] = cmin1[nt];
        }
    }
    __syncthreads();

    if (tid < 128) {
        float rv = fminf(fminf(redr[tid * 4], redr[tid * 4 + 1]),
                         fminf(redr[tid * 4 + 2], redr[tid * 4 + 3]));
        atomicMin((int*)&g_rowmin[(size_t)b * NN + n0 + tid], __float_as_int(rv));
    }
    {
        float cv = fminf(redc[tid * 2], redc[tid * 2 + 1]);
        atomicMin((int*)&g_colmin[(size_t)b * MM + m0 + tid], __float_as_int(cv));
    }
}

// Multi-block weighted reduction -> atomicAdd into g_acc.
__global__ void partial_final_kernel(const float* __restrict__ w1,
                                     const float* __restrict__ w2) {
    __shared__ double sh[256];
    int tid = threadIdx.x;
    int gid = blockIdx.x * 256 + tid;
    int stride = gridDim.x * 256;
    double s = 0.0;
    for (int i = gid; i < BB * NN; i += stride)
        s += (double)w1[i] * sqrtf(g_rowmin[i]);
    for (int i = gid; i < BB * MM; i += stride)
        s += (double)w2[i] * sqrtf(g_colmin[i]);
    sh[tid] = s;
    __syncthreads();
    for (int off = 128; off > 0; off >>= 1) {
        if (tid < off) sh[tid] += sh[tid + off];
        __syncthreads();
    }
    if (tid == 0) atomicAdd(&g_acc, sh[0]);
}

__global__ void writeout_kernel(float* __restrict__ out) {
    out[0] = (float)(g_acc * 0.5);
}

extern "C" void kernel_launch(void* const* d_in, const int* in_sizes, int n_in,
                              void* d_out, int out_size) {
    const float* set1 = (const float*)d_in[0];
    const float* set2 = (const float*)d_in[1];
    const float* w1   = (const float*)d_in[2];
    const float* w2   = (const float*)d_in[3];
    float* out = (float*)d_out;

    init_mins_kernel<<<(BB * NN + 255) / 256, 256>>>();

    dim3 ngrid((BB * NN) / 8, 2, 1);
    norms_kernel<<<ngrid, 256>>>(set1, set2);

    cudaFuncSetAttribute(chamfer_tile_kernel,
                         cudaFuncAttributeMaxDynamicSharedMemorySize, SMEM_BYTES);
    dim3 tgrid(MM / TM, NN / TN, BB);
    chamfer_tile_kernel<<<tgrid, 256, SMEM_BYTES>>>(set1, set2);

    partial_final_kernel<<<64, 256>>>(w1, w2);
    writeout_kernel<<<1, 1>>>(out);
}

// round 7
// speedup vs baseline: 5.6889x; 1.5364x over previous
#include <cuda_runtime.h>
#include <cuda_fp16.h>
#include <math.h>
#include <stdint.h>

// Problem shape (fixed by the dataset)
#define BB 8
#define NN 4096
#define MM 4096
#define CC 128

#define TN 128     // CTA tile: set1 rows
#define TM 256     // CTA tile: set2 cols
#define KSL 64     // channels per K-slice (2 slices)

#define RSB 144    // smem row stride bytes (64 fp16 = 128B + 16B pad) -> ldmatrix conflict-free
#define A_SLICE (TN * RSB)          // 18432
#define B_SLICE (TM * RSB)          // 36864
#define BUF (A_SLICE + B_SLICE)     // 55296
#define SMEM_BYTES (2 * BUF)        // 110592

#define FINF __int_as_float(0x7F800000)

// Scratch (no allocations allowed in kernel_launch)
__device__ float  g_rowmin[BB * NN];
__device__ float  g_colmin[BB * MM];
__device__ float  g_x2[BB * NN];
__device__ float  g_y2[BB * MM];
__device__ double g_acc;
__device__ __half g_xh[BB * NN * CC];
__device__ __half g_yh[BB * MM * CC];

__global__ void init_mins_kernel() {
    int i = blockIdx.x * blockDim.x + threadIdx.x;
    if (i < BB * NN) g_rowmin[i] = FINF;
    if (i < BB * MM) g_colmin[i] = FINF;
    if (i == 0) g_acc = 0.0;
}

// One warp per point: convert fp32 -> fp16 AND compute norm from the fp16 values
// (so d2 = |x|^2 + |y|^2 - 2xy is exactly |x-y|^2 of the rounded points).
__global__ void convert_norms_kernel(const float* __restrict__ X, const float* __restrict__ Y) {
    int gwarp = (blockIdx.x * blockDim.x + threadIdx.x) >> 5;
    int lane = threadIdx.x & 31;
    const float* src = blockIdx.y ? Y : X;
    __half* dsth = blockIdx.y ? g_yh : g_xh;
    float* dst2 = blockIdx.y ? g_y2 : g_x2;
    if (gwarp >= BB * NN) return;
    const float2* row = (const float2*)(src + (size_t)gwarp * CC);
    __half2* out = (__half2*)(dsth + (size_t)gwarp * CC);
    float s = 0.0f;
#pragma unroll
    for (int q = 0; q < 2; q++) {
        float2 v = row[lane + 32 * q];
        __half2 h = __floats2half2_rn(v.x, v.y);
        out[lane + 32 * q] = h;
        float2 bk = __half22float2(h);
        s += bk.x * bk.x + bk.y * bk.y;
    }
#pragma unroll
    for (int off = 16; off > 0; off >>= 1)
        s += __shfl_xor_sync(0xFFFFFFFFu, s, off);
    if (lane == 0) dst2[gwarp] = s;
}

// ---------------- PTX helpers (family-portable only) ----------------
__device__ __forceinline__ uint32_t smem_u32(const void* p) {
    return (uint32_t)__cvta_generic_to_shared(p);
}
__device__ __forceinline__ void cp16(uint32_t saddr, const void* gaddr) {
    asm volatile("cp.async.cg.shared.global [%0], [%1], 16;\n" :: "r"(saddr), "l"(gaddr));
}
__device__ __forceinline__ void cp_commit() { asm volatile("cp.async.commit_group;\n"); }
template <int N>
__device__ __forceinline__ void cp_wait() { asm volatile("cp.async.wait_group %0;\n" :: "n"(N)); }

__device__ __forceinline__ void ldsm4(uint32_t& r0, uint32_t& r1, uint32_t& r2, uint32_t& r3,
                                      uint32_t addr) {
    asm volatile("ldmatrix.sync.aligned.m8n8.x4.shared.b16 {%0,%1,%2,%3}, [%4];"
                 : "=r"(r0), "=r"(r1), "=r"(r2), "=r"(r3) : "r"(addr));
}

__device__ __forceinline__ void mma_f16(float& c0, float& c1, float& c2, float& c3,
                                        uint32_t a0, uint32_t a1, uint32_t a2, uint32_t a3,
                                        uint32_t b0, uint32_t b1) {
    asm volatile(
        "mma.sync.aligned.m16n8k16.row.col.f32.f16.f16.f32 "
        "{%0,%1,%2,%3}, {%4,%5,%6,%7}, {%8,%9}, {%0,%1,%2,%3};"
        : "+f"(c0), "+f"(c1), "+f"(c2), "+f"(c3)
        : "r"(a0), "r"(a1), "r"(a2), "r"(a3), "r"(b0), "r"(b1));
}

// ---------------- main fused kernel ----------------
// Grid: (MM/TM=16, NN/TN=32, BB), 256 threads = 8 warps.
// Warp layout: wn = w>>2 (2 row-halves of 64), wm = w&3 (4 col-slices of 64).
// Each warp: 64x64 tile = 4 m16 x 8 n8 tiles of m16n8k16 fp16 (fp32 acc).
__global__ void __launch_bounds__(256, 1)
chamfer_tile_kernel() {
    extern __shared__ char smem[];
    uint32_t sbase = smem_u32(smem);

    const int b  = blockIdx.z;
    const int n0 = blockIdx.y * TN;
    const int m0 = blockIdx.x * TM;

    const __half* xb = g_xh + ((size_t)b * NN + n0) * CC;
    const __half* yb = g_yh + ((size_t)b * MM + m0) * CC;

    const int tid  = threadIdx.x;
    const int lane = tid & 31;
    const int w    = tid >> 5;
    const int g    = lane >> 2;
    const int t    = lane & 3;
    const int wn   = w >> 2;
    const int wm   = w & 3;

    // --- stage both K-slices (fp16, 16B chunks, one commit group each) ---
#pragma unroll
    for (int s = 0; s < 2; s++) {
        uint32_t abuf = sbase + s * BUF;
        uint32_t bbuf = abuf + A_SLICE;
#pragma unroll
        for (int p = 0; p < 4; p++) {           // A: 1024 chunks
            int c = p * 256 + tid;
            int row = c >> 3, col = c & 7;
            cp16(abuf + row * RSB + col * 16, xb + (size_t)row * CC + s * KSL + col * 8);
        }
#pragma unroll
        for (int p = 0; p < 8; p++) {           // B: 2048 chunks
            int c = p * 256 + tid;
            int row = c >> 3, col = c & 7;
            cp16(bbuf + row * RSB + col * 16, yb + (size_t)row * CC + s * KSL + col * 8);
        }
        cp_commit();
    }

    float acc[4][8][4];
#pragma unroll
    for (int mt = 0; mt < 4; mt++)
#pragma unroll
        for (int nt = 0; nt < 8; nt++)
#pragma unroll
            for (int c = 0; c < 4; c++)
                acc[mt][nt][c] = 0.0f;

    // ldmatrix lane->address mapping
    const int arow = lane & 15;          // A: rows 0..15 within m16 tile
    const int akc  = lane >> 4;          // A: k-chunk (lo/hi 16B)
    const int brow = ((lane >> 4) << 3) + (lane & 7);  // B: rows within 16-row pair
    const int bkc  = (lane >> 3) & 1;    // B: k-chunk

#pragma unroll
    for (int s = 0; s < 2; s++) {
        if (s == 0) cp_wait<1>(); else cp_wait<0>();
        __syncthreads();
        uint32_t abuf = sbase + s * BUF;
        uint32_t bbuf = abuf + A_SLICE;

#pragma unroll
        for (int ks = 0; ks < 4; ks++) {         // 4 x k16 per slice
            uint32_t a[4][4], bf[8][2];
#pragma unroll
            for (int mt = 0; mt < 4; mt++)
                ldsm4(a[mt][0], a[mt][1], a[mt][2], a[mt][3],
                      abuf + (wn * 64 + mt * 16 + arow) * RSB + ks * 32 + akc * 16);
#pragma unroll
            for (int p = 0; p < 4; p++) {
                uint32_t r0, r1, r2, r3;
                ldsm4(r0, r1, r2, r3,
                      bbuf + (wm * 64 + p * 16 + brow) * RSB + ks * 32 + bkc * 16);
                bf[2 * p][0] = r0; bf[2 * p][1] = r1;
                bf[2 * p + 1][0] = r2; bf[2 * p + 1][1] = r3;
            }
#pragma unroll
            for (int mt = 0; mt < 4; mt++)
#pragma unroll
                for (int nt = 0; nt < 8; nt++)
                    mma_f16(acc[mt][nt][0], acc[mt][nt][1], acc[mt][nt][2], acc[mt][nt][3],
                            a[mt][0], a[mt][1], a[mt][2], a[mt][3],
                            bf[nt][0], bf[nt][1]);
        }
    }

    // Epilogue. C fragment (m16n8k16): c0=(g,2t) c1=(g,2t+1) c2=(g+8,2t) c3=(g+8,2t+1).
    float y2a[8], y2b[8];
#pragma unroll
    for (int nt = 0; nt < 8; nt++) {
        int c0 = m0 + wm * 64 + nt * 8 + 2 * t;
        y2a[nt] = g_y2[(size_t)b * MM + c0];
        y2b[nt] = g_y2[(size_t)b * MM + c0 + 1];
    }

    float rmin0[4], rmin1[4];
    float cmin0[8], cmin1[8];
#pragma unroll
    for (int q = 0; q < 8; q++) { cmin0[q] = FINF; cmin1[q] = FINF; }

#pragma unroll
    for (int mt = 0; mt < 4; mt++) {
        int r0 = n0 + wn * 64 + mt * 16 + g;
        float x2a = g_x2[(size_t)b * NN + r0];
        float x2b = g_x2[(size_t)b * NN + r0 + 8];
        float ra = FINF, rb = FINF;
#pragma unroll
        for (int nt = 0; nt < 8; nt++) {
            float d00 = fmaxf(x2a + y2a[nt] - 2.0f * acc[mt][nt][0], 0.0f);
            float d01 = fmaxf(x2a + y2b[nt] - 2.0f * acc[mt][nt][1], 0.0f);
            float d10 = fmaxf(x2b + y2a[nt] - 2.0f * acc[mt][nt][2], 0.0f);
            float d11 = fmaxf(x2b + y2b[nt] - 2.0f * acc[mt][nt][3], 0.0f);
            ra = fminf(ra, fminf(d00, d01));
            rb = fminf(rb, fminf(d10, d11));
            cmin0[nt] = fminf(cmin0[nt], fminf(d00, d10));
            cmin1[nt] = fminf(cmin1[nt], fminf(d01, d11));
        }
        rmin0[mt] = ra;
        rmin1[mt] = rb;
    }

    // Row mins: reduce across t (lane bits 0,1)
#pragma unroll
    for (int mt = 0; mt < 4; mt++) {
#pragma unroll
        for (int off = 1; off <= 2; off <<= 1) {
            rmin0[mt] = fminf(rmin0[mt], __shfl_xor_sync(0xFFFFFFFFu, rmin0[mt], off));
            rmin1[mt] = fminf(rmin1[mt], __shfl_xor_sync(0xFFFFFFFFu, rmin1[mt], off));
        }
    }
    // Col mins: reduce across g (lane bits 2,3,4)
#pragma unroll
    for (int nt = 0; nt < 8; nt++) {
#pragma unroll
        for (int off = 4; off <= 16; off <<= 1) {
            cmin0[nt] = fminf(cmin0[nt], __shfl_xor_sync(0xFFFFFFFFu, cmin0[nt], off));
            cmin1[nt] = fminf(cmin1[nt], __shfl_xor_sync(0xFFFFFFFFu, cmin1[nt], off));
        }
    }

    // Cross-warp reduction via smem scratch
    float* redr = (float*)smem;           // [128][4] rowmin per wm
    float* redc = (float*)smem + 512;     // [256][2] colmin per wn
    __syncthreads();   // all mainloop smem reads done

    if (t == 0) {
#pragma unroll
        for (int mt = 0; mt < 4; mt++) {
            int r = wn * 64 + mt * 16 + g;
            redr[r * 4 + wm] = rmin0[mt];
            redr[(r + 8) * 4 + wm] = rmin1[mt];
        }
    }
    if (g == 0) {
#pragma unroll
        for (int nt = 0; nt < 8; nt++) {
            int c = wm * 64 + nt * 8 + 2 * t;
            redc[c * 2 + wn] = cmin0[nt];
            redc[(c + 1) * 2 + wn] = cmin1[nt];
        }
    }
    __syncthreads();

    if (tid < 128) {
        float rv = fminf(fminf(redr[tid * 4], redr[tid * 4 + 1]),
                         fminf(redr[tid * 4 + 2], redr[tid * 4 + 3]));
        atomicMin((int*)&g_rowmin[(size_t)b * NN + n0 + tid], __float_as_int(rv));
    }
    {
        float cv = fminf(redc[tid * 2], redc[tid * 2 + 1]);
        atomicMin((int*)&g_colmin[(size_t)b * MM + m0 + tid], __float_as_int(cv));
    }
}

// Multi-block weighted reduction -> atomicAdd into g_acc.
__global__ void partial_final_kernel(const float* __restrict__ w1,
                                     const float* __restrict__ w2) {
    __shared__ double sh[256];
    int tid = threadIdx.x;
    int gid = blockIdx.x * 256 + tid;
    int stride = gridDim.x * 256;
    double s = 0.0;
    for (int i = gid; i < BB * NN; i += stride)
        s += (double)w1[i] * sqrtf(g_rowmin[i]);
    for (int i = gid; i < BB * MM; i += stride)
        s += (double)w2[i] * sqrtf(g_colmin[i]);
    sh[tid] = s;
    __syncthreads();
    for (int off = 128; off > 0; off >>= 1) {
        if (tid < off) sh[tid] += sh[tid + off];
        __syncthreads();
    }
    if (tid == 0) atomicAdd(&g_acc, sh[0]);
}

__global__ void writeout_kernel(float* __restrict__ out) {
    out[0] = (float)(g_acc * 0.5);
}

extern "C" void kernel_launch(void* const* d_in, const int* in_sizes, int n_in,
                              void* d_out, int out_size) {
    const float* set1 = (const float*)d_in[0];
    const float* set2 = (const float*)d_in[1];
    const float* w1   = (const float*)d_in[2];
    const float* w2   = (const float*)d_in[3];
    float* out = (float*)d_out;

    init_mins_kernel<<<(BB * NN + 255) / 256, 256>>>();

    dim3 ngrid((BB * NN) / 8, 2, 1);
    convert_norms_kernel<<<ngrid, 256>>>(set1, set2);

    cudaFuncSetAttribute(chamfer_tile_kernel,
                         cudaFuncAttributeMaxDynamicSharedMemorySize, SMEM_BYTES);
    dim3 tgrid(MM / TM, NN / TN, BB);
    chamfer_tile_kernel<<<tgrid, 256, SMEM_BYTES>>>();

    partial_final_kernel<<<64, 256>>>(w1, w2);
    writeout_kernel<<<1, 1>>>(out);
}

// round 8
// speedup vs baseline: 6.3732x; 1.1203x over previous
#include <cuda_runtime.h>
#include <cuda_fp16.h>
#include <math.h>
#include <stdint.h>

// Problem shape (fixed by the dataset)
#define BB 8
#define NN 4096
#define MM 4096
#define CC 128

#define TN 128     // tile rows (set1)
#define TM 256     // tile cols (set2)
#define TT_TOTAL 4096   // total tiles = (MM/TM)*(NN/TN)*BB = 16*32*8

#define RSB 144    // smem row stride bytes (64 fp16 = 128B + 16B pad)
#define ASL 18432  // A slice bytes (128 rows * 144)
#define BSL 36864  // B slice bytes (256 rows * 144)
#define ABUF (2 * ASL)      // 36864 (both K-slices)
#define BBUF (2 * BSL)      // 73728
#define BOFF ABUF           // B buffers start
#define SCR  (ABUF + 2 * BBUF)            // scratch offset: 184320
#define SMEM_BYTES (SCR + 4096)           // 188416

#define FINF __int_as_float(0x7F800000)

// Scratch (no allocations allowed in kernel_launch)
__device__ float  g_rowmin[BB * NN];
__device__ float  g_colmin[BB * MM];
__device__ float  g_x2[BB * NN];
__device__ float  g_y2[BB * MM];
__device__ double g_acc;
__device__ __half g_xh[BB * NN * CC];
__device__ __half g_yh[BB * MM * CC];

__global__ void init_mins_kernel() {
    int i = blockIdx.x * blockDim.x + threadIdx.x;
    if (i < BB * NN) g_rowmin[i] = FINF;
    if (i < BB * MM) g_colmin[i] = FINF;
    if (i == 0) g_acc = 0.0;
}

// One warp per point: fp32 -> fp16 + norm of the ROUNDED values
// (so d2 = |x|^2+|y|^2-2xy is exactly |x-y|^2 of the rounded points).
__global__ void convert_norms_kernel(const float* __restrict__ X, const float* __restrict__ Y) {
    int gwarp = (blockIdx.x * blockDim.x + threadIdx.x) >> 5;
    int lane = threadIdx.x & 31;
    const float* src = blockIdx.y ? Y : X;
    __half* dsth = blockIdx.y ? g_yh : g_xh;
    float* dst2 = blockIdx.y ? g_y2 : g_x2;
    if (gwarp >= BB * NN) return;
    const float2* row = (const float2*)(src + (size_t)gwarp * CC);
    __half2* out = (__half2*)(dsth + (size_t)gwarp * CC);
    float s = 0.0f;
#pragma unroll
    for (int q = 0; q < 2; q++) {
        float2 v = row[lane + 32 * q];
        __half2 h = __floats2half2_rn(v.x, v.y);
        out[lane + 32 * q] = h;
        float2 bk = __half22float2(h);
        s += bk.x * bk.x + bk.y * bk.y;
    }
#pragma unroll
    for (int off = 16; off > 0; off >>= 1)
        s += __shfl_xor_sync(0xFFFFFFFFu, s, off);
    if (lane == 0) dst2[gwarp] = s;
}

// ---------------- PTX helpers (family-portable only) ----------------
__device__ __forceinline__ uint32_t smem_u32(const void* p) {
    return (uint32_t)__cvta_generic_to_shared(p);
}
__device__ __forceinline__ void cp16(uint32_t saddr, const void* gaddr) {
    asm volatile("cp.async.cg.shared.global [%0], [%1], 16;\n" :: "r"(saddr), "l"(gaddr));
}
__device__ __forceinline__ void cp_commit() { asm volatile("cp.async.commit_group;\n"); }
template <int N>
__device__ __forceinline__ void cp_wait() { asm volatile("cp.async.wait_group %0;\n" :: "n"(N)); }

__device__ __forceinline__ void ldsm4(uint32_t& r0, uint32_t& r1, uint32_t& r2, uint32_t& r3,
                                      uint32_t addr) {
    asm volatile("ldmatrix.sync.aligned.m8n8.x4.shared.b16 {%0,%1,%2,%3}, [%4];"
                 : "=r"(r0), "=r"(r1), "=r"(r2), "=r"(r3) : "r"(addr));
}

__device__ __forceinline__ void mma_f16(float& c0, float& c1, float& c2, float& c3,
                                        uint32_t a0, uint32_t a1, uint32_t a2, uint32_t a3,
                                        uint32_t b0, uint32_t b1) {
    asm volatile(
        "mma.sync.aligned.m16n8k16.row.col.f32.f16.f16.f32 "
        "{%0,%1,%2,%3}, {%4,%5,%6,%7}, {%8,%9}, {%0,%1,%2,%3};"
        : "+f"(c0), "+f"(c1), "+f"(c2), "+f"(c3)
        : "r"(a0), "r"(a1), "r"(a2), "r"(a3), "r"(b0), "r"(b1));
}

// ---------------- persistent fused kernel ----------------
// Tile index tt: m-tile = tt&15 (fastest), n-tile = (tt>>4)&31, batch = tt>>9.
// Each CTA takes a contiguous chunk -> A tile reused across consecutive m-tiles.
__global__ void __launch_bounds__(256, 1)
chamfer_tile_kernel() {
    extern __shared__ char smem[];
    uint32_t sbase = smem_u32(smem);

    const int tid  = threadIdx.x;
    const int lane = tid & 31;
    const int w    = tid >> 5;
    const int g    = lane >> 2;
    const int t    = lane & 3;
    const int wn   = w >> 2;
    const int wm   = w & 3;

    const int chunk = (TT_TOTAL + gridDim.x - 1) / gridDim.x;
    const int t0 = blockIdx.x * chunk;
    const int t1 = min(t0 + chunk, TT_TOTAL);
    if (t0 >= TT_TOTAL) return;

    // ldmatrix lane->address mapping
    const int arow = lane & 15;
    const int akc  = lane >> 4;
    const int brow = ((lane >> 4) << 3) + (lane & 7);
    const int bkc  = (lane >> 3) & 1;

    // stage A (both K-slices) for row index nrow = (b*32 + ntile)
    auto stageA = [&](int tt) {
        int b = tt >> 9, n0 = ((tt >> 4) & 31) * TN;
        const __half* xb = g_xh + ((size_t)b * NN + n0) * CC;
#pragma unroll
        for (int p = 0; p < 8; p++) {     // 2048 chunks
            int c = p * 256 + tid;
            int s = c >> 10;
            int r = (c & 1023) >> 3, col = c & 7;
            cp16(sbase + s * ASL + r * RSB + col * 16,
                 xb + (size_t)r * CC + s * 64 + col * 8);
        }
    };
    auto stageB = [&](int tt) {
        int b = tt >> 9, m0 = (tt & 15) * TM;
        const __half* yb = g_yh + ((size_t)b * MM + m0) * CC;
        uint32_t bbuf = sbase + BOFF + (tt & 1) * BBUF;
#pragma unroll
        for (int p = 0; p < 16; p++) {    // 4096 chunks
            int c = p * 256 + tid;
            int s = c >> 11;
            int r = (c & 2047) >> 3, col = c & 7;
            cp16(bbuf + s * BSL + r * RSB + col * 16,
                 yb + (size_t)r * CC + s * 64 + col * 8);
        }
    };

    for (int tt = t0; tt < t1; tt++) {
        const int b  = tt >> 9;
        const int n0 = ((tt >> 4) & 31) * TN;
        const int m0 = (tt & 15) * TM;
        const int row = tt >> 4;

        const bool fresh = (tt == t0) || ((tt & 15) == 0);
        if (fresh) {                      // new A row: stage A + B(tt), full stall
            stageA(tt);
            stageB(tt);
            cp_commit();
        }
        const bool prefnext = (tt + 1 < t1) && (((tt + 1) >> 4) == row);
        if (prefnext) { stageB(tt + 1); cp_commit(); }

        if (prefnext) cp_wait<1>(); else cp_wait<0>();
        __syncthreads();

        const uint32_t bbase = sbase + BOFF + (tt & 1) * BBUF;

        float acc[4][8][4];
#pragma unroll
        for (int mt = 0; mt < 4; mt++)
#pragma unroll
            for (int nt = 0; nt < 8; nt++)
#pragma unroll
                for (int c = 0; c < 4; c++)
                    acc[mt][nt][c] = 0.0f;

#pragma unroll
        for (int s = 0; s < 2; s++) {
            uint32_t abuf = sbase + s * ASL;
            uint32_t bbuf = bbase + s * BSL;
#pragma unroll
            for (int ks = 0; ks < 4; ks++) {
                uint32_t a[4][4], bf[8][2];
#pragma unroll
                for (int mt = 0; mt < 4; mt++)
                    ldsm4(a[mt][0], a[mt][1], a[mt][2], a[mt][3],
                          abuf + (wn * 64 + mt * 16 + arow) * RSB + ks * 32 + akc * 16);
#pragma unroll
                for (int p = 0; p < 4; p++) {
                    uint32_t r0, r1, r2, r3;
                    ldsm4(r0, r1, r2, r3,
                          bbuf + (wm * 64 + p * 16 + brow) * RSB + ks * 32 + bkc * 16);
                    bf[2 * p][0] = r0; bf[2 * p][1] = r1;
                    bf[2 * p + 1][0] = r2; bf[2 * p + 1][1] = r3;
                }
#pragma unroll
                for (int mt = 0; mt < 4; mt++)
#pragma unroll
                    for (int nt = 0; nt < 8; nt++)
                        mma_f16(acc[mt][nt][0], acc[mt][nt][1], acc[mt][nt][2], acc[mt][nt][3],
                                a[mt][0], a[mt][1], a[mt][2], a[mt][3],
                                bf[nt][0], bf[nt][1]);
            }
        }

        // Epilogue. C frag: c0=(g,2t) c1=(g,2t+1) c2=(g+8,2t) c3=(g+8,2t+1).
        float y2a[8], y2b[8];
#pragma unroll
        for (int nt = 0; nt < 8; nt++) {
            int c0 = m0 + wm * 64 + nt * 8 + 2 * t;
            y2a[nt] = g_y2[(size_t)b * MM + c0];
            y2b[nt] = g_y2[(size_t)b * MM + c0 + 1];
        }

        float rmin0[4], rmin1[4];
        float cmin0[8], cmin1[8];
#pragma unroll
        for (int q = 0; q < 8; q++) { cmin0[q] = FINF; cmin1[q] = FINF; }

#pragma unroll
        for (int mt = 0; mt < 4; mt++) {
            int r0 = n0 + wn * 64 + mt * 16 + g;
            float x2a = g_x2[(size_t)b * NN + r0];
            float x2b = g_x2[(size_t)b * NN + r0 + 8];
            float ra = FINF, rb = FINF;
#pragma unroll
            for (int nt = 0; nt < 8; nt++) {
                float d00 = fmaxf(x2a + y2a[nt] - 2.0f * acc[mt][nt][0], 0.0f);
                float d01 = fmaxf(x2a + y2b[nt] - 2.0f * acc[mt][nt][1], 0.0f);
                float d10 = fmaxf(x2b + y2a[nt] - 2.0f * acc[mt][nt][2], 0.0f);
                float d11 = fmaxf(x2b + y2b[nt] - 2.0f * acc[mt][nt][3], 0.0f);
                ra = fminf(ra, fminf(d00, d01));
                rb = fminf(rb, fminf(d10, d11));
                cmin0[nt] = fminf(cmin0[nt], fminf(d00, d10));
                cmin1[nt] = fminf(cmin1[nt], fminf(d01, d11));
            }
            rmin0[mt] = ra;
            rmin1[mt] = rb;
        }

#pragma unroll
        for (int mt = 0; mt < 4; mt++) {
#pragma unroll
            for (int off = 1; off <= 2; off <<= 1) {
                rmin0[mt] = fminf(rmin0[mt], __shfl_xor_sync(0xFFFFFFFFu, rmin0[mt], off));
                rmin1[mt] = fminf(rmin1[mt], __shfl_xor_sync(0xFFFFFFFFu, rmin1[mt], off));
            }
        }
#pragma unroll
        for (int nt = 0; nt < 8; nt++) {
#pragma unroll
            for (int off = 4; off <= 16; off <<= 1) {
                cmin0[nt] = fminf(cmin0[nt], __shfl_xor_sync(0xFFFFFFFFu, cmin0[nt], off));
                cmin1[nt] = fminf(cmin1[nt], __shfl_xor_sync(0xFFFFFFFFu, cmin1[nt], off));
            }
        }

        float* redr = (float*)(smem + SCR);      // [128][4]
        float* redc = redr + 512;                // [256][2]

        if (t == 0) {
#pragma unroll
            for (int mt = 0; mt < 4; mt++) {
                int r = wn * 64 + mt * 16 + g;
                redr[r * 4 + wm] = rmin0[mt];
                redr[(r + 8) * 4 + wm] = rmin1[mt];
            }
        }
        if (g == 0) {
#pragma unroll
            for (int nt = 0; nt < 8; nt++) {
                int c = wm * 64 + nt * 8 + 2 * t;
                redc[c * 2 + wn] = cmin0[nt];
                redc[(c + 1) * 2 + wn] = cmin1[nt];
            }
        }
        __syncthreads();

        if (tid < 128) {
            float rv = fminf(fminf(redr[tid * 4], redr[tid * 4 + 1]),
                             fminf(redr[tid * 4 + 2], redr[tid * 4 + 3]));
            atomicMin((int*)&g_rowmin[(size_t)b * NN + n0 + tid], __float_as_int(rv));
        }
        {
            float cv = fminf(redc[tid * 2], redc[tid * 2 + 1]);
            atomicMin((int*)&g_colmin[(size_t)b * MM + m0 + tid], __float_as_int(cv));
        }
        __syncthreads();   // scratch/A/B safe to overwrite next iteration
    }
}

// Multi-block weighted reduction -> atomicAdd into g_acc.
__global__ void partial_final_kernel(const float* __restrict__ w1,
                                     const float* __restrict__ w2) {
    __shared__ double sh[256];
    int tid = threadIdx.x;
    int gid = blockIdx.x * 256 + tid;
    int stride = gridDim.x * 256;
    double s = 0.0;
    for (int i = gid; i < BB * NN; i += stride)
        s += (double)w1[i] * sqrtf(g_rowmin[i]);
    for (int i = gid; i < BB * MM; i += stride)
        s += (double)w2[i] * sqrtf(g_colmin[i]);
    sh[tid] = s;
    __syncthreads();
    for (int off = 128; off > 0; off >>= 1) {
        if (tid < off) sh[tid] += sh[tid + off];
        __syncthreads();
    }
    if (tid == 0) atomicAdd(&g_acc, sh[0]);
}

__global__ void writeout_kernel(float* __restrict__ out) {
    out[0] = (float)(g_acc * 0.5);
}

extern "C" void kernel_launch(void* const* d_in, const int* in_sizes, int n_in,
                              void* d_out, int out_size) {
    const float* set1 = (const float*)d_in[0];
    const float* set2 = (const float*)d_in[1];
    const float* w1   = (const float*)d_in[2];
    const float* w2   = (const float*)d_in[3];
    float* out = (float*)d_out;

    int nsm = 148;
    cudaDeviceGetAttribute(&nsm, cudaDevAttrMultiProcessorCount, 0);

    init_mins_kernel<<<(BB * NN + 255) / 256, 256>>>();

    dim3 ngrid((BB * NN) / 8, 2, 1);
    convert_norms_kernel<<<ngrid, 256>>>(set1, set2);

    cudaFuncSetAttribute(chamfer_tile_kernel,
                         cudaFuncAttributeMaxDynamicSharedMemorySize, SMEM_BYTES);
    chamfer_tile_kernel<<<nsm, 256, SMEM_BYTES>>>();

    partial_final_kernel<<<64, 256>>>(w1, w2);
    writeout_kernel<<<1, 1>>>(out);
}

// round 9
// speedup vs baseline: 6.8627x; 1.0768x over previous
#include <cuda_runtime.h>
#include <cuda_fp16.h>
#include <math.h>
#include <stdint.h>

// Problem shape (fixed by the dataset)
#define BB 8
#define NN 4096
#define MM 4096
#define CC 128

#define TN 128     // tile rows (set1)
#define TM 256     // tile cols (set2)
#define TT_TOTAL 4096   // (MM/TM)*(NN/TN)*BB = 16*32*8

#define RSB 144    // smem row stride bytes (64 fp16 = 128B + 16B pad)
#define ASL 18432  // A K-slice bytes (128 rows * 144)
#define BSL 36864  // B K-slice bytes (256 rows * 144)
#define ABUF (2 * ASL)      // 36864 per A buffer (both K-slices)
#define BBUF (2 * BSL)      // 73728 per B buffer
#define BOFF (2 * ABUF)     // 73728: B buffers start after 2 A buffers
#define SCR  (BOFF + 2 * BBUF)            // 221184
#define SMEM_BYTES (SCR + 4096)           // 225280

#define FINF __int_as_float(0x7F800000)

// Scratch (no allocations allowed in kernel_launch)
__device__ float  g_rowmin[BB * NN];
__device__ float  g_colmin[BB * MM];
__device__ float  g_x2[BB * NN];
__device__ float  g_y2[BB * MM];
__device__ double g_acc;
__device__ int    g_done = 0;
__device__ __half g_xh[BB * NN * CC];
__device__ __half g_yh[BB * MM * CC];

// One warp per point: fp32 -> fp16 + norm of the ROUNDED values.
// Also initializes min buffers and the accumulator (fused init).
__global__ void convert_norms_kernel(const float* __restrict__ X, const float* __restrict__ Y) {
    int gwarp = (blockIdx.x * blockDim.x + threadIdx.x) >> 5;
    int lane = threadIdx.x & 31;

    // fused init: each block covers 8 points -> init 8 mins
    if (threadIdx.x < 8) {
        int idx = blockIdx.x * 8 + threadIdx.x;
        if (blockIdx.y) g_colmin[idx] = FINF; else g_rowmin[idx] = FINF;
        if (idx == 0 && blockIdx.y == 0) { g_acc = 0.0; g_done = 0; }
    }

    const float* src = blockIdx.y ? Y : X;
    __half* dsth = blockIdx.y ? g_yh : g_xh;
    float* dst2 = blockIdx.y ? g_y2 : g_x2;
    if (gwarp >= BB * NN) return;
    const float2* row = (const float2*)(src + (size_t)gwarp * CC);
    __half2* out = (__half2*)(dsth + (size_t)gwarp * CC);
    float s = 0.0f;
#pragma unroll
    for (int q = 0; q < 2; q++) {
        float2 v = row[lane + 32 * q];
        __half2 h = __floats2half2_rn(v.x, v.y);
        out[lane + 32 * q] = h;
        float2 bk = __half22float2(h);
        s += bk.x * bk.x + bk.y * bk.y;
    }
#pragma unroll
    for (int off = 16; off > 0; off >>= 1)
        s += __shfl_xor_sync(0xFFFFFFFFu, s, off);
    if (lane == 0) dst2[gwarp] = s;
}

// ---------------- PTX helpers (family-portable only) ----------------
__device__ __forceinline__ uint32_t smem_u32(const void* p) {
    return (uint32_t)__cvta_generic_to_shared(p);
}
__device__ __forceinline__ void cp16(uint32_t saddr, const void* gaddr) {
    asm volatile("cp.async.cg.shared.global [%0], [%1], 16;\n" :: "r"(saddr), "l"(gaddr));
}
__device__ __forceinline__ void cp_commit() { asm volatile("cp.async.commit_group;\n"); }
template <int N>
__device__ __forceinline__ void cp_wait() { asm volatile("cp.async.wait_group %0;\n" :: "n"(N)); }

__device__ __forceinline__ void ldsm4(uint32_t& r0, uint32_t& r1, uint32_t& r2, uint32_t& r3,
                                      uint32_t addr) {
    asm volatile("ldmatrix.sync.aligned.m8n8.x4.shared.b16 {%0,%1,%2,%3}, [%4];"
                 : "=r"(r0), "=r"(r1), "=r"(r2), "=r"(r3) : "r"(addr));
}

__device__ __forceinline__ void mma_f16(float& c0, float& c1, float& c2, float& c3,
                                        uint32_t a0, uint32_t a1, uint32_t a2, uint32_t a3,
                                        uint32_t b0, uint32_t b1) {
    asm volatile(
        "mma.sync.aligned.m16n8k16.row.col.f32.f16.f16.f32 "
        "{%0,%1,%2,%3}, {%4,%5,%6,%7}, {%8,%9}, {%0,%1,%2,%3};"
        : "+f"(c0), "+f"(c1), "+f"(c2), "+f"(c3)
        : "r"(a0), "r"(a1), "r"(a2), "r"(a3), "r"(b0), "r"(b1));
}

// ---------------- persistent fused kernel ----------------
// Tile index tt: m-tile = tt&15 (fastest), n-tile = (tt>>4)&31, batch = tt>>9.
// A double-buffered by row parity; B double-buffered by tile parity.
__global__ void __launch_bounds__(256, 1)
chamfer_tile_kernel() {
    extern __shared__ char smem[];
    uint32_t sbase = smem_u32(smem);

    const int tid  = threadIdx.x;
    const int lane = tid & 31;
    const int w    = tid >> 5;
    const int g    = lane >> 2;
    const int t    = lane & 3;
    const int wn   = w >> 2;
    const int wm   = w & 3;

    const int chunk = (TT_TOTAL + gridDim.x - 1) / gridDim.x;
    const int t0 = blockIdx.x * chunk;
    const int t1 = min(t0 + chunk, TT_TOTAL);
    if (t0 >= TT_TOTAL) return;

    const int arow = lane & 15;
    const int akc  = lane >> 4;
    const int brow = ((lane >> 4) << 3) + (lane & 7);
    const int bkc  = (lane >> 3) & 1;

    auto stageA = [&](int tt) {   // into A buffer (row parity)
        int b = tt >> 9, n0 = ((tt >> 4) & 31) * TN;
        uint32_t abuf = sbase + (((tt >> 4) & 1) ? ABUF : 0);
        const __half* xb = g_xh + ((size_t)b * NN + n0) * CC;
#pragma unroll
        for (int p = 0; p < 8; p++) {
            int c = p * 256 + tid;
            int s = c >> 10;
            int r = (c & 1023) >> 3, col = c & 7;
            cp16(abuf + s * ASL + r * RSB + col * 16,
                 xb + (size_t)r * CC + s * 64 + col * 8);
        }
    };
    auto stageB = [&](int tt) {   // into B buffer (tile parity)
        int b = tt >> 9, m0 = (tt & 15) * TM;
        const __half* yb = g_yh + ((size_t)b * MM + m0) * CC;
        uint32_t bbuf = sbase + BOFF + (tt & 1) * BBUF;
#pragma unroll
        for (int p = 0; p < 16; p++) {
            int c = p * 256 + tid;
            int s = c >> 11;
            int r = (c & 2047) >> 3, col = c & 7;
            cp16(bbuf + s * BSL + r * RSB + col * 16,
                 yb + (size_t)r * CC + s * 64 + col * 8);
        }
    };

    float rmin0[4], rmin1[4];   // persist across m-tiles of a row

    for (int tt = t0; tt < t1; tt++) {
        const int b   = tt >> 9;
        const int n0  = ((tt >> 4) & 31) * TN;
        const int m0  = (tt & 15) * TM;
        const int row = tt >> 4;

        if (tt == t0) { stageA(tt); stageB(tt); cp_commit(); }

        const bool pref = (tt + 1 < t1);
        if (pref) {
            if (((tt + 1) >> 4) != row) stageA(tt + 1);
            stageB(tt + 1);
            cp_commit();
        }
        if (pref) cp_wait<1>(); else cp_wait<0>();
        __syncthreads();

        const uint32_t abase = sbase + ((row & 1) ? ABUF : 0);
        const uint32_t bbase = sbase + BOFF + (tt & 1) * BBUF;

        float acc[4][8][4];
#pragma unroll
        for (int mt = 0; mt < 4; mt++)
#pragma unroll
            for (int nt = 0; nt < 8; nt++)
#pragma unroll
                for (int c = 0; c < 4; c++)
                    acc[mt][nt][c] = 0.0f;

#pragma unroll
        for (int s = 0; s < 2; s++) {
            uint32_t abuf = abase + s * ASL;
            uint32_t bbuf = bbase + s * BSL;
#pragma unroll
            for (int ks = 0; ks < 4; ks++) {
                uint32_t a[4][4], bf[8][2];
#pragma unroll
                for (int mt = 0; mt < 4; mt++)
                    ldsm4(a[mt][0], a[mt][1], a[mt][2], a[mt][3],
                          abuf + (wn * 64 + mt * 16 + arow) * RSB + ks * 32 + akc * 16);
#pragma unroll
                for (int p = 0; p < 4; p++) {
                    uint32_t r0, r1, r2, r3;
                    ldsm4(r0, r1, r2, r3,
                          bbuf + (wm * 64 + p * 16 + brow) * RSB + ks * 32 + bkc * 16);
                    bf[2 * p][0] = r0; bf[2 * p][1] = r1;
                    bf[2 * p + 1][0] = r2; bf[2 * p + 1][1] = r3;
                }
#pragma unroll
                for (int mt = 0; mt < 4; mt++)
#pragma unroll
                    for (int nt = 0; nt < 8; nt++)
                        mma_f16(acc[mt][nt][0], acc[mt][nt][1], acc[mt][nt][2], acc[mt][nt][3],
                                a[mt][0], a[mt][1], a[mt][2], a[mt][3],
                                bf[nt][0], bf[nt][1]);
            }
        }

        // Epilogue. C frag: c0=(g,2t) c1=(g,2t+1) c2=(g+8,2t) c3=(g+8,2t+1).
        const bool rowstart = (tt == t0) || ((tt & 15) == 0);
        const bool rowend   = (tt == t1 - 1) || ((tt & 15) == 15);
        if (rowstart) {
#pragma unroll
            for (int mt = 0; mt < 4; mt++) { rmin0[mt] = FINF; rmin1[mt] = FINF; }
        }

        float y2a[8], y2b[8];
#pragma unroll
        for (int nt = 0; nt < 8; nt++) {
            int c0 = m0 + wm * 64 + nt * 8 + 2 * t;
            y2a[nt] = g_y2[(size_t)b * MM + c0];
            y2b[nt] = g_y2[(size_t)b * MM + c0 + 1];
        }

        float cmin0[8], cmin1[8];
#pragma unroll
        for (int q = 0; q < 8; q++) { cmin0[q] = FINF; cmin1[q] = FINF; }

#pragma unroll
        for (int mt = 0; mt < 4; mt++) {
            int r0 = n0 + wn * 64 + mt * 16 + g;
            float x2a = g_x2[(size_t)b * NN + r0];
            float x2b = g_x2[(size_t)b * NN + r0 + 8];
            float ra = rmin0[mt], rb = rmin1[mt];
#pragma unroll
            for (int nt = 0; nt < 8; nt++) {
                // no clamp here: min/clamp commute; clamp at flush
                float d00 = x2a + y2a[nt] - 2.0f * acc[mt][nt][0];
                float d01 = x2a + y2b[nt] - 2.0f * acc[mt][nt][1];
                float d10 = x2b + y2a[nt] - 2.0f * acc[mt][nt][2];
                float d11 = x2b + y2b[nt] - 2.0f * acc[mt][nt][3];
                ra = fminf(ra, fminf(d00, d01));
                rb = fminf(rb, fminf(d10, d11));
                cmin0[nt] = fminf(cmin0[nt], fminf(d00, d10));
                cmin1[nt] = fminf(cmin1[nt], fminf(d01, d11));
            }
            rmin0[mt] = ra;
            rmin1[mt] = rb;
        }

        // Col mins: reduce across g (lane bits 2,3,4), flush every tile
#pragma unroll
        for (int nt = 0; nt < 8; nt++) {
#pragma unroll
            for (int off = 4; off <= 16; off <<= 1) {
                cmin0[nt] = fminf(cmin0[nt], __shfl_xor_sync(0xFFFFFFFFu, cmin0[nt], off));
                cmin1[nt] = fminf(cmin1[nt], __shfl_xor_sync(0xFFFFFFFFu, cmin1[nt], off));
            }
        }

        float* redr = (float*)(smem + SCR);      // [128][4]
        float* redc = redr + 512;                // [256][2]

        if (g == 0) {
#pragma unroll
            for (int nt = 0; nt < 8; nt++) {
                int c = wm * 64 + nt * 8 + 2 * t;
                redc[c * 2 + wn] = cmin0[nt];
                redc[(c + 1) * 2 + wn] = cmin1[nt];
            }
        }

        if (rowend) {
            // Row mins: reduce across t (lane bits 0,1) once per row
            float r0v[4], r1v[4];
#pragma unroll
            for (int mt = 0; mt < 4; mt++) {
                r0v[mt] = rmin0[mt]; r1v[mt] = rmin1[mt];
#pragma unroll
                for (int off = 1; off <= 2; off <<= 1) {
                    r0v[mt] = fminf(r0v[mt], __shfl_xor_sync(0xFFFFFFFFu, r0v[mt], off));
                    r1v[mt] = fminf(r1v[mt], __shfl_xor_sync(0xFFFFFFFFu, r1v[mt], off));
                }
            }
            if (t == 0) {
#pragma unroll
                for (int mt = 0; mt < 4; mt++) {
                    int r = wn * 64 + mt * 16 + g;
                    redr[r * 4 + wm] = r0v[mt];
                    redr[(r + 8) * 4 + wm] = r1v[mt];
                }
            }
        }
        __syncthreads();

        {
            float cv = fminf(redc[tid * 2], redc[tid * 2 + 1]);
            cv = fmaxf(cv, 0.0f);
            atomicMin((int*)&g_colmin[(size_t)b * MM + m0 + tid], __float_as_int(cv));
        }
        if (rowend && tid < 128) {
            float rv = fminf(fminf(redr[tid * 4], redr[tid * 4 + 1]),
                             fminf(redr[tid * 4 + 2], redr[tid * 4 + 3]));
            rv = fmaxf(rv, 0.0f);
            atomicMin((int*)&g_rowmin[(size_t)b * NN + n0 + tid], __float_as_int(rv));
        }
        __syncthreads();   // scratch safe to overwrite next iteration
    }
}

// Weighted reduction; last block writes the output (fused writeout).
__global__ void partial_final_kernel(const float* __restrict__ w1,
                                     const float* __restrict__ w2,
                                     float* __restrict__ out) {
    __shared__ double sh[256];
    int tid = threadIdx.x;
    int gid = blockIdx.x * 256 + tid;
    int stride = gridDim.x * 256;
    double s = 0.0;
    for (int i = gid; i < BB * NN; i += stride)
        s += (double)w1[i] * sqrtf(g_rowmin[i]);
    for (int i = gid; i < BB * MM; i += stride)
        s += (double)w2[i] * sqrtf(g_colmin[i]);
    sh[tid] = s;
    __syncthreads();
    for (int off = 128; off > 0; off >>= 1) {
        if (tid < off) sh[tid] += sh[tid + off];
        __syncthreads();
    }
    if (tid == 0) {
        atomicAdd(&g_acc, sh[0]);
        __threadfence();
        int done = atomicAdd(&g_done, 1);
        if (done == (int)gridDim.x - 1) {
            double total = atomicAdd(&g_acc, 0.0);   // atomic read, all adds visible
            out[0] = (float)(total * 0.5);
            g_done = 0;                              // deterministic across replays
        }
    }
}

extern "C" void kernel_launch(void* const* d_in, const int* in_sizes, int n_in,
                              void* d_out, int out_size) {
    const float* set1 = (const float*)d_in[0];
    const float* set2 = (const float*)d_in[1];
    const float* w1   = (const float*)d_in[2];
    const float* w2   = (const float*)d_in[3];
    float* out = (float*)d_out;

    int nsm = 148;
    cudaDeviceGetAttribute(&nsm, cudaDevAttrMultiProcessorCount, 0);

    dim3 ngrid((BB * NN) / 8, 2, 1);
    convert_norms_kernel<<<ngrid, 256>>>(set1, set2);

    cudaFuncSetAttribute(chamfer_tile_kernel,
                         cudaFuncAttributeMaxDynamicSharedMemorySize, SMEM_BYTES);
    chamfer_tile_kernel<<<nsm, 256, SMEM_BYTES>>>();

    partial_final_kernel<<<64, 256>>>(w1, w2, out);
}

// round 10
// speedup vs baseline: 7.7344x; 1.1270x over previous
#include <cuda_runtime.h>
#include <cuda_fp16.h>
#include <math.h>
#include <stdint.h>

// Problem shape (fixed by the dataset)
#define BB 8
#define NN 4096
#define MM 4096
#define CC 128

#define TN 128     // tile rows (set1, A, streamed)
#define TM 256     // tile cols (set2, B, resident per column)
#define TT_TOTAL 4096   // 32 n-tiles * 16 m-tiles * 8 batches

#define RSB 144    // smem row stride bytes (64 fp16 = 128B + 16B pad)
#define ASL 18432  // A K-slice bytes (128 rows * 144)
#define BSL 36864  // B K-slice bytes (256 rows * 144)
#define ABUF (2 * ASL)      // 36864 per A buffer (both K-slices)
#define BBUF (2 * BSL)      // 73728 (single B buffer)
#define AOFF BBUF           // A buffers after B
#define SCR  (AOFF + 2 * ABUF)            // 147456
#define SMEM_BYTES (SCR + 4096)           // 151552

#define FINF __int_as_float(0x7F800000)

// Scratch (no allocations allowed in kernel_launch)
__device__ float  g_rowmin[BB * NN];
__device__ float  g_colmin[BB * MM];
__device__ float  g_x2[BB * NN];
__device__ float  g_y2[BB * MM];
__device__ double g_acc;
__device__ int    g_done = 0;
__device__ __half g_xh[BB * NN * CC];
__device__ __half g_yh[BB * MM * CC];

// One warp per point: fp32 -> fp16 + norm of the ROUNDED values.
// Also initializes min buffers and the accumulator (fused init).
__global__ void convert_norms_kernel(const float* __restrict__ X, const float* __restrict__ Y) {
    int gwarp = (blockIdx.x * blockDim.x + threadIdx.x) >> 5;
    int lane = threadIdx.x & 31;

    if (threadIdx.x < 8) {
        int idx = blockIdx.x * 8 + threadIdx.x;
        if (blockIdx.y) g_colmin[idx] = FINF; else g_rowmin[idx] = FINF;
        if (idx == 0 && blockIdx.y == 0) { g_acc = 0.0; g_done = 0; }
    }

    const float* src = blockIdx.y ? Y : X;
    __half* dsth = blockIdx.y ? g_yh : g_xh;
    float* dst2 = blockIdx.y ? g_y2 : g_x2;
    if (gwarp >= BB * NN) return;
    const float2* row = (const float2*)(src + (size_t)gwarp * CC);
    __half2* out = (__half2*)(dsth + (size_t)gwarp * CC);
    float s = 0.0f;
#pragma unroll
    for (int q = 0; q < 2; q++) {
        float2 v = row[lane + 32 * q];
        __half2 h = __floats2half2_rn(v.x, v.y);
        out[lane + 32 * q] = h;
        float2 bk = __half22float2(h);
        s += bk.x * bk.x + bk.y * bk.y;
    }
#pragma unroll
    for (int off = 16; off > 0; off >>= 1)
        s += __shfl_xor_sync(0xFFFFFFFFu, s, off);
    if (lane == 0) dst2[gwarp] = s;
}

// ---------------- PTX helpers (family-portable only) ----------------
__device__ __forceinline__ uint32_t smem_u32(const void* p) {
    return (uint32_t)__cvta_generic_to_shared(p);
}
__device__ __forceinline__ void cp16(uint32_t saddr, const void* gaddr) {
    asm volatile("cp.async.cg.shared.global [%0], [%1], 16;\n" :: "r"(saddr), "l"(gaddr));
}
__device__ __forceinline__ void cp_commit() { asm volatile("cp.async.commit_group;\n"); }
template <int N>
__device__ __forceinline__ void cp_wait() { asm volatile("cp.async.wait_group %0;\n" :: "n"(N)); }

__device__ __forceinline__ void ldsm4(uint32_t& r0, uint32_t& r1, uint32_t& r2, uint32_t& r3,
                                      uint32_t addr) {
    asm volatile("ldmatrix.sync.aligned.m8n8.x4.shared.b16 {%0,%1,%2,%3}, [%4];"
                 : "=r"(r0), "=r"(r1), "=r"(r2), "=r"(r3) : "r"(addr));
}

__device__ __forceinline__ void mma_f16(float& c0, float& c1, float& c2, float& c3,
                                        uint32_t a0, uint32_t a1, uint32_t a2, uint32_t a3,
                                        uint32_t b0, uint32_t b1) {
    asm volatile(
        "mma.sync.aligned.m16n8k16.row.col.f32.f16.f16.f32 "
        "{%0,%1,%2,%3}, {%4,%5,%6,%7}, {%8,%9}, {%0,%1,%2,%3};"
        : "+f"(c0), "+f"(c1), "+f"(c2), "+f"(c3)
        : "r"(a0), "r"(a1), "r"(a2), "r"(a3), "r"(b0), "r"(b1));
}

// ---------------- persistent fused kernel ----------------
// Tile index tt: n-tile = tt&31 (FASTEST), column cc = tt>>5; m-tile = cc&15,
// batch = cc>>4. B tile resident across a 32-tile column; A streamed/prefetched.
__global__ void __launch_bounds__(256, 1)
chamfer_tile_kernel() {
    extern __shared__ char smem[];
    uint32_t sbase = smem_u32(smem);

    const int tid  = threadIdx.x;
    const int lane = tid & 31;
    const int w    = tid >> 5;
    const int g    = lane >> 2;
    const int t    = lane & 3;
    const int wn   = w >> 2;
    const int wm   = w & 3;

    const int chunk = (TT_TOTAL + gridDim.x - 1) / gridDim.x;
    const int t0 = blockIdx.x * chunk;
    const int t1 = min(t0 + chunk, TT_TOTAL);
    if (t0 >= TT_TOTAL) return;

    const int arow = lane & 15;
    const int akc  = lane >> 4;
    const int brow = ((lane >> 4) << 3) + (lane & 7);
    const int bkc  = (lane >> 3) & 1;

    auto stageA = [&](int tt) {   // A tile (tile parity buffer): 2048 cp16
        int cc = tt >> 5, b = cc >> 4;
        int n0 = (tt & 31) * TN;
        uint32_t abuf = sbase + AOFF + (tt & 1) * ABUF;
        const __half* xb = g_xh + ((size_t)b * NN + n0) * CC;
#pragma unroll
        for (int p = 0; p < 8; p++) {
            int c = p * 256 + tid;
            int s = c >> 10;
            int r = (c & 1023) >> 3, col = c & 7;
            cp16(abuf + s * ASL + r * RSB + col * 16,
                 xb + (size_t)r * CC + s * 64 + col * 8);
        }
    };
    auto stageB = [&](int cc) {   // B tile (single buffer): 4096 cp16
        int b = cc >> 4, m0 = (cc & 15) * TM;
        const __half* yb = g_yh + ((size_t)b * MM + m0) * CC;
#pragma unroll
        for (int p = 0; p < 16; p++) {
            int c = p * 256 + tid;
            int s = c >> 11;
            int r = (c & 2047) >> 3, col = c & 7;
            cp16(sbase + s * BSL + r * RSB + col * 16,
                 yb + (size_t)r * CC + s * 64 + col * 8);
        }
    };

    float cmin0[8], cmin1[8];   // persist across the column (B cols fixed)
    float y2a[8], y2b[8];       // y norms, loaded once per column

    for (int tt = t0; tt < t1; tt++) {
        const int cc = tt >> 5;
        const int b  = cc >> 4;
        const int n0 = (tt & 31) * TN;
        const int m0 = (cc & 15) * TM;

        const bool colstart = (tt == t0) || ((tt & 31) == 0);
        if (colstart) {          // new column: stage B + A(tt), full stall
            stageB(cc);
            stageA(tt);
            cp_commit();
#pragma unroll
            for (int q = 0; q < 8; q++) { cmin0[q] = FINF; cmin1[q] = FINF; }
#pragma unroll
            for (int nt = 0; nt < 8; nt++) {
                int c0 = m0 + wm * 64 + nt * 8 + 2 * t;
                y2a[nt] = g_y2[(size_t)b * MM + c0];
                y2b[nt] = g_y2[(size_t)b * MM + c0 + 1];
            }
        }

        const bool pref = (tt + 1 < t1) && (((tt + 1) & 31) != 0);
        if (pref) { stageA(tt + 1); cp_commit(); }
        if (pref) cp_wait<1>(); else cp_wait<0>();
        __syncthreads();

        const uint32_t abase = sbase + AOFF + (tt & 1) * ABUF;

        float acc[4][8][4];
#pragma unroll
        for (int mt = 0; mt < 4; mt++)
#pragma unroll
            for (int nt = 0; nt < 8; nt++)
#pragma unroll
                for (int c = 0; c < 4; c++)
                    acc[mt][nt][c] = 0.0f;

#pragma unroll
        for (int s = 0; s < 2; s++) {
            uint32_t abuf = abase + s * ASL;
            uint32_t bbuf = sbase + s * BSL;
#pragma unroll
            for (int ks = 0; ks < 4; ks++) {
                uint32_t a[4][4], bf[8][2];
#pragma unroll
                for (int mt = 0; mt < 4; mt++)
                    ldsm4(a[mt][0], a[mt][1], a[mt][2], a[mt][3],
                          abuf + (wn * 64 + mt * 16 + arow) * RSB + ks * 32 + akc * 16);
#pragma unroll
                for (int p = 0; p < 4; p++) {
                    uint32_t r0, r1, r2, r3;
                    ldsm4(r0, r1, r2, r3,
                          bbuf + (wm * 64 + p * 16 + brow) * RSB + ks * 32 + bkc * 16);
                    bf[2 * p][0] = r0; bf[2 * p][1] = r1;
                    bf[2 * p + 1][0] = r2; bf[2 * p + 1][1] = r3;
                }
#pragma unroll
                for (int mt = 0; mt < 4; mt++)
#pragma unroll
                    for (int nt = 0; nt < 8; nt++)
                        mma_f16(acc[mt][nt][0], acc[mt][nt][1], acc[mt][nt][2], acc[mt][nt][3],
                                a[mt][0], a[mt][1], a[mt][2], a[mt][3],
                                bf[nt][0], bf[nt][1]);
            }
        }

        // Epilogue. C frag: c0=(g,2t) c1=(g,2t+1) c2=(g+8,2t) c3=(g+8,2t+1).
        float rmin0[4], rmin1[4];
#pragma unroll
        for (int mt = 0; mt < 4; mt++) {
            int r0 = n0 + wn * 64 + mt * 16 + g;
            float x2a = g_x2[(size_t)b * NN + r0];
            float x2b = g_x2[(size_t)b * NN + r0 + 8];
            float ra = FINF, rb = FINF;
#pragma unroll
            for (int nt = 0; nt < 8; nt++) {
                // no clamp here: min/clamp commute; clamp at flush
                float d00 = x2a + y2a[nt] - 2.0f * acc[mt][nt][0];
                float d01 = x2a + y2b[nt] - 2.0f * acc[mt][nt][1];
                float d10 = x2b + y2a[nt] - 2.0f * acc[mt][nt][2];
                float d11 = x2b + y2b[nt] - 2.0f * acc[mt][nt][3];
                ra = fminf(ra, fminf(d00, d01));
                rb = fminf(rb, fminf(d10, d11));
                cmin0[nt] = fminf(cmin0[nt], fminf(d00, d10));
                cmin1[nt] = fminf(cmin1[nt], fminf(d01, d11));
            }
            rmin0[mt] = ra;
            rmin1[mt] = rb;
        }

        float* redr = (float*)(smem + SCR);      // [128][4]
        float* redc = redr + 512;                // [256][2]

        // Row mins: reduce across t (lane bits 0,1), flush EVERY tile (16 shfl)
#pragma unroll
        for (int mt = 0; mt < 4; mt++) {
#pragma unroll
            for (int off = 1; off <= 2; off <<= 1) {
                rmin0[mt] = fminf(rmin0[mt], __shfl_xor_sync(0xFFFFFFFFu, rmin0[mt], off));
                rmin1[mt] = fminf(rmin1[mt], __shfl_xor_sync(0xFFFFFFFFu, rmin1[mt], off));
            }
        }
        if (t == 0) {
#pragma unroll
            for (int mt = 0; mt < 4; mt++) {
                int r = wn * 64 + mt * 16 + g;
                redr[r * 4 + wm] = rmin0[mt];
                redr[(r + 8) * 4 + wm] = rmin1[mt];
            }
        }

        // Col mins: reduce across g + flush only at COLUMN END (80 shfl / 32 tiles)
        const bool colend = (tt == t1 - 1) || ((tt & 31) == 31);
        if (colend) {
            float c0v[8], c1v[8];
#pragma unroll
            for (int nt = 0; nt < 8; nt++) {
                c0v[nt] = cmin0[nt]; c1v[nt] = cmin1[nt];
#pragma unroll
                for (int off = 4; off <= 16; off <<= 1) {
                    c0v[nt] = fminf(c0v[nt], __shfl_xor_sync(0xFFFFFFFFu, c0v[nt], off));
                    c1v[nt] = fminf(c1v[nt], __shfl_xor_sync(0xFFFFFFFFu, c1v[nt], off));
                }
            }
            if (g == 0) {
#pragma unroll
                for (int nt = 0; nt < 8; nt++) {
                    int c = wm * 64 + nt * 8 + 2 * t;
                    redc[c * 2 + wn] = c0v[nt];
                    redc[(c + 1) * 2 + wn] = c1v[nt];
                }
            }
        }
        __syncthreads();

        if (tid < 128) {
            float rv = fminf(fminf(redr[tid * 4], redr[tid * 4 + 1]),
                             fminf(redr[tid * 4 + 2], redr[tid * 4 + 3]));
            rv = fmaxf(rv, 0.0f);
            atomicMin((int*)&g_rowmin[(size_t)b * NN + n0 + tid], __float_as_int(rv));
        }
        if (colend) {
            float cv = fminf(redc[tid * 2], redc[tid * 2 + 1]);
            cv = fmaxf(cv, 0.0f);
            atomicMin((int*)&g_colmin[(size_t)b * MM + m0 + tid], __float_as_int(cv));
        }
        __syncthreads();   // scratch/B/A safe to overwrite next iteration
    }
}

// Weighted reduction; last block writes the output (fused writeout).
__global__ void partial_final_kernel(const float* __restrict__ w1,
                                     const float* __restrict__ w2,
                                     float* __restrict__ out) {
    __shared__ double sh[256];
    int tid = threadIdx.x;
    int gid = blockIdx.x * 256 + tid;
    int stride = gridDim.x * 256;
    double s = 0.0;
    for (int i = gid; i < BB * NN; i += stride)
        s += (double)w1[i] * sqrtf(g_rowmin[i]);
    for (int i = gid; i < BB * MM; i += stride)
        s += (double)w2[i] * sqrtf(g_colmin[i]);
    sh[tid] = s;
    __syncthreads();
    for (int off = 128; off > 0; off >>= 1) {
        if (tid < off) sh[tid] += sh[tid + off];
        __syncthreads();
    }
    if (tid == 0) {
        atomicAdd(&g_acc, sh[0]);
        __threadfence();
        int done = atomicAdd(&g_done, 1);
        if (done == (int)gridDim.x - 1) {
            double total = atomicAdd(&g_acc, 0.0);
            out[0] = (float)(total * 0.5);
            g_done = 0;
        }
    }
}

extern "C" void kernel_launch(void* const* d_in, const int* in_sizes, int n_in,
                              void* d_out, int out_size) {
    const float* set1 = (const float*)d_in[0];
    const float* set2 = (const float*)d_in[1];
    const float* w1   = (const float*)d_in[2];
    const float* w2   = (const float*)d_in[3];
    float* out = (float*)d_out;

    int nsm = 148;
    cudaDeviceGetAttribute(&nsm, cudaDevAttrMultiProcessorCount, 0);

    dim3 ngrid((BB * NN) / 8, 2, 1);
    convert_norms_kernel<<<ngrid, 256>>>(set1, set2);

    cudaFuncSetAttribute(chamfer_tile_kernel,
                         cudaFuncAttributeMaxDynamicSharedMemorySize, SMEM_BYTES);
    chamfer_tile_kernel<<<nsm, 256, SMEM_BYTES>>>();

    partial_final_kernel<<<64, 256>>>(w1, w2, out);
}

// round 11
// speedup vs baseline: 8.1761x; 1.0571x over previous
#include <cuda_runtime.h>
#include <cuda.h>
#include <cuda_fp16.h>
#include <math.h>
#include <stdint.h>

// Problem shape (fixed by the dataset)
#define BB 8
#define NN 4096
#define MM 4096
#define CC 128

#define TN 128     // tile rows (set1, A, streamed)
#define TM 256     // tile cols (set2, B, resident per column)
#define TT_TOTAL 4096   // 32 n-tiles * 16 m-tiles * 8 batches

#define FINF __int_as_float(0x7F800000)

// ---- TMA kernel smem layout (SW128 tiles, 128B rows, no pad) ----
#define T_BSL 32768            // B K-slice (256 rows * 128B)
#define T_ASL 16384            // A K-slice (128 rows * 128B)
#define T_AOFF (2 * T_BSL)     // 65536: A buffers after B
#define T_ABUF (2 * T_ASL)     // 32768 per A buffer
#define T_SCR (T_AOFF + 2 * T_ABUF)   // 131072
#define T_MBAR (T_SCR + 4096)         // 135168
#define T_SMEM (T_MBAR + 64)          // 135232

// ---- cp.async fallback kernel layout (R10) ----
#define RSB 144
#define ASL 18432
#define BSL 36864
#define ABUF (2 * ASL)
#define BBUF (2 * BSL)
#define AOFF BBUF
#define SCR  (AOFF + 2 * ABUF)
#define SMEM_BYTES (SCR + 4096)

// Scratch (no allocations allowed in kernel_launch)
__device__ float  g_rowmin[BB * NN];
__device__ float  g_colmin[BB * MM];
__device__ float  g_x2[BB * NN];
__device__ float  g_y2[BB * MM];
__device__ double g_acc;
__device__ int    g_done = 0;
__device__ __half g_xh[BB * NN * CC];
__device__ __half g_yh[BB * MM * CC];

// One warp per point: fp32 -> fp16 + norm of the ROUNDED values; fused init.
__global__ void convert_norms_kernel(const float* __restrict__ X, const float* __restrict__ Y) {
    int gwarp = (blockIdx.x * blockDim.x + threadIdx.x) >> 5;
    int lane = threadIdx.x & 31;

    if (threadIdx.x < 8) {
        int idx = blockIdx.x * 8 + threadIdx.x;
        if (blockIdx.y) g_colmin[idx] = FINF; else g_rowmin[idx] = FINF;
        if (idx == 0 && blockIdx.y == 0) { g_acc = 0.0; g_done = 0; }
    }

    const float* src = blockIdx.y ? Y : X;
    __half* dsth = blockIdx.y ? g_yh : g_xh;
    float* dst2 = blockIdx.y ? g_y2 : g_x2;
    if (gwarp >= BB * NN) return;

    float4 v = ((const float4*)(src + (size_t)gwarp * CC))[lane];
    __half2 h0 = __floats2half2_rn(v.x, v.y);
    __half2 h1 = __floats2half2_rn(v.z, v.w);
    uint2 st;
    st.x = *(const unsigned*)&h0;
    st.y = *(const unsigned*)&h1;
    ((uint2*)(dsth + (size_t)gwarp * CC))[lane] = st;

    float2 b0 = __half22float2(h0), b1 = __half22float2(h1);
    float s = b0.x * b0.x + b0.y * b0.y + b1.x * b1.x + b1.y * b1.y;
#pragma unroll
    for (int off = 16; off > 0; off >>= 1)
        s += __shfl_xor_sync(0xFFFFFFFFu, s, off);
    if (lane == 0) dst2[gwarp] = s;
}

// ---------------- PTX helpers ----------------
__device__ __forceinline__ uint32_t smem_u32(const void* p) {
    return (uint32_t)__cvta_generic_to_shared(p);
}
__device__ __forceinline__ void cp16(uint32_t saddr, const void* gaddr) {
    asm volatile("cp.async.cg.shared.global [%0], [%1], 16;\n" :: "r"(saddr), "l"(gaddr));
}
__device__ __forceinline__ void cp_commit() { asm volatile("cp.async.commit_group;\n"); }
template <int N>
__device__ __forceinline__ void cp_wait() { asm volatile("cp.async.wait_group %0;\n" :: "n"(N)); }

__device__ __forceinline__ void ldsm4(uint32_t& r0, uint32_t& r1, uint32_t& r2, uint32_t& r3,
                                      uint32_t addr) {
    asm volatile("ldmatrix.sync.aligned.m8n8.x4.shared.b16 {%0,%1,%2,%3}, [%4];"
                 : "=r"(r0), "=r"(r1), "=r"(r2), "=r"(r3) : "r"(addr));
}
__device__ __forceinline__ void mma_f16(float& c0, float& c1, float& c2, float& c3,
                                        uint32_t a0, uint32_t a1, uint32_t a2, uint32_t a3,
                                        uint32_t b0, uint32_t b1) {
    asm volatile(
        "mma.sync.aligned.m16n8k16.row.col.f32.f16.f16.f32 "
        "{%0,%1,%2,%3}, {%4,%5,%6,%7}, {%8,%9}, {%0,%1,%2,%3};"
        : "+f"(c0), "+f"(c1), "+f"(c2), "+f"(c3)
        : "r"(a0), "r"(a1), "r"(a2), "r"(a3), "r"(b0), "r"(b1));
}
__device__ __forceinline__ void mbar_init(uint32_t a, uint32_t cnt) {
    asm volatile("mbarrier.init.shared.b64 [%0], %1;" :: "r"(a), "r"(cnt) : "memory");
}
__device__ __forceinline__ void mbar_expect(uint32_t a, uint32_t bytes) {
    asm volatile("mbarrier.arrive.expect_tx.shared.b64 _, [%0], %1;" :: "r"(a), "r"(bytes) : "memory");
}
__device__ __forceinline__ void mbar_wait(uint32_t a, uint32_t parity) {
    asm volatile(
        "{\n\t.reg .pred P1;\n\t"
        "WL%=:\n\t"
        "mbarrier.try_wait.parity.acquire.cta.shared::cta.b64 P1, [%0], %1, 0x989680;\n\t"
        "@P1 bra.uni WD%=;\n\t"
        "bra.uni WL%=;\n\t"
        "WD%=:\n\t}"
        :: "r"(a), "r"(parity) : "memory");
}
__device__ __forceinline__ void tma2d(uint32_t dst, const void* tmap, int x, int y, uint32_t mbar) {
    asm volatile(
        "cp.async.bulk.tensor.2d.shared::cta.global.tile.mbarrier::complete_tx::bytes "
        "[%0], [%1, {%2, %3}], [%4];"
        :: "r"(dst), "l"(tmap), "r"(x), "r"(y), "r"(mbar) : "memory");
}

// ================= TMA persistent kernel =================
// Tile index tt: n-tile = tt&31 (fastest), column cc = tt>>5; m-tile = cc&15,
// batch = cc>>4. B resident per column; A double-buffered via TMA + mbarrier.
__global__ void __launch_bounds__(256, 1)
chamfer_tma_kernel(const __grid_constant__ CUtensorMap tmX,
                   const __grid_constant__ CUtensorMap tmY) {
    extern __shared__ __align__(1024) char smem[];
    uint32_t sbase = smem_u32(smem);

    const int tid  = threadIdx.x;
    const int lane = tid & 31;
    const int w    = tid >> 5;
    const int g    = lane >> 2;
    const int t    = lane & 3;
    const int wn   = w >> 2;
    const int wm   = w & 3;

    const int chunk = (TT_TOTAL + gridDim.x - 1) / gridDim.x;
    const int t0 = blockIdx.x * chunk;
    const int t1 = min(t0 + chunk, TT_TOTAL);
    if (t0 >= TT_TOTAL) return;

    const int arow = lane & 15;
    const int akc  = lane >> 4;
    const int brow = ((lane >> 4) << 3) + (lane & 7);
    const int bkc  = (lane >> 3) & 1;

    if (tid == 0) { mbar_init(sbase + T_MBAR, 1); mbar_init(sbase + T_MBAR + 8, 1); }
    __syncthreads();

    int ph[2] = {0, 0};
    float cmin0[8], cmin1[8];
    float y2a[8], y2b[8];

    for (int tt = t0; tt < t1; tt++) {
        const int cc = tt >> 5;
        const int b  = cc >> 4;
        const int n0 = (tt & 31) * TN;
        const int m0 = (cc & 15) * TM;
        const int p  = tt & 1;

        const bool colstart = (tt == t0) || ((tt & 31) == 0);
        if (colstart) {
            if (tid == 0) {
                mbar_expect(sbase + T_MBAR + p * 8, 2 * T_BSL + 2 * T_ASL);
                tma2d(sbase,          &tmY, 0,  b * MM + m0, sbase + T_MBAR + p * 8);
                tma2d(sbase + T_BSL,  &tmY, 64, b * MM + m0, sbase + T_MBAR + p * 8);
                uint32_t abuf = sbase + T_AOFF + p * T_ABUF;
                tma2d(abuf,          &tmX, 0,  b * NN + n0, sbase + T_MBAR + p * 8);
                tma2d(abuf + T_ASL,  &tmX, 64, b * NN + n0, sbase + T_MBAR + p * 8);
            }
#pragma unroll
            for (int q = 0; q < 8; q++) { cmin0[q] = FINF; cmin1[q] = FINF; }
#pragma unroll
            for (int nt = 0; nt < 8; nt++) {
                int c0 = m0 + wm * 64 + nt * 8 + 2 * t;
                y2a[nt] = g_y2[(size_t)b * MM + c0];
                y2b[nt] = g_y2[(size_t)b * MM + c0 + 1];
            }
        }
        // prefetch next A within the column
        if (tid == 0 && (tt + 1 < t1) && (((tt + 1) & 31) != 0)) {
            int pn = p ^ 1;
            int nn0 = ((tt + 1) & 31) * TN;
            uint32_t abuf = sbase + T_AOFF + pn * T_ABUF;
            mbar_expect(sbase + T_MBAR + pn * 8, 2 * T_ASL);
            tma2d(abuf,         &tmX, 0,  b * NN + nn0, sbase + T_MBAR + pn * 8);
            tma2d(abuf + T_ASL, &tmX, 64, b * NN + nn0, sbase + T_MBAR + pn * 8);
        }

        mbar_wait(sbase + T_MBAR + p * 8, ph[p]);
        ph[p] ^= 1;

        const uint32_t abase = sbase + T_AOFF + p * T_ABUF;

        float acc[4][8][4];
#pragma unroll
        for (int mt = 0; mt < 4; mt++)
#pragma unroll
            for (int nt = 0; nt < 8; nt++)
#pragma unroll
                for (int c = 0; c < 4; c++)
                    acc[mt][nt][c] = 0.0f;

#pragma unroll
        for (int s = 0; s < 2; s++) {
            uint32_t abuf = abase + s * T_ASL;
            uint32_t bbuf = sbase + s * T_BSL;
#pragma unroll
            for (int ks = 0; ks < 4; ks++) {
                uint32_t a[4][4], bf[8][2];
#pragma unroll
                for (int mt = 0; mt < 4; mt++) {
                    int r = wn * 64 + mt * 16 + arow;
                    ldsm4(a[mt][0], a[mt][1], a[mt][2], a[mt][3],
                          abuf + r * 128 + (((ks * 2 + akc) ^ (r & 7)) << 4));
                }
#pragma unroll
                for (int pp = 0; pp < 4; pp++) {
                    int r = wm * 64 + pp * 16 + brow;
                    uint32_t r0, r1, r2, r3;
                    ldsm4(r0, r1, r2, r3,
                          bbuf + r * 128 + (((ks * 2 + bkc) ^ (r & 7)) << 4));
                    bf[2 * pp][0] = r0; bf[2 * pp][1] = r1;
                    bf[2 * pp + 1][0] = r2; bf[2 * pp + 1][1] = r3;
                }
#pragma unroll
                for (int mt = 0; mt < 4; mt++)
#pragma unroll
                    for (int nt = 0; nt < 8; nt++)
                        mma_f16(acc[mt][nt][0], acc[mt][nt][1], acc[mt][nt][2], acc[mt][nt][3],
                                a[mt][0], a[mt][1], a[mt][2], a[mt][3],
                                bf[nt][0], bf[nt][1]);
            }
        }

        // Epilogue. C frag: c0=(g,2t) c1=(g,2t+1) c2=(g+8,2t) c3=(g+8,2t+1).
        float rmin0[4], rmin1[4];
#pragma unroll
        for (int mt = 0; mt < 4; mt++) {
            int r0 = n0 + wn * 64 + mt * 16 + g;
            float x2a = g_x2[(size_t)b * NN + r0];
            float x2b = g_x2[(size_t)b * NN + r0 + 8];
            float ra = FINF, rb = FINF;
#pragma unroll
            for (int nt = 0; nt < 8; nt++) {
                float d00 = x2a + y2a[nt] - 2.0f * acc[mt][nt][0];
                float d01 = x2a + y2b[nt] - 2.0f * acc[mt][nt][1];
                float d10 = x2b + y2a[nt] - 2.0f * acc[mt][nt][2];
                float d11 = x2b + y2b[nt] - 2.0f * acc[mt][nt][3];
                ra = fminf(ra, fminf(d00, d01));
                rb = fminf(rb, fminf(d10, d11));
                cmin0[nt] = fminf(cmin0[nt], fminf(d00, d10));
                cmin1[nt] = fminf(cmin1[nt], fminf(d01, d11));
            }
            rmin0[mt] = ra;
            rmin1[mt] = rb;
        }

        float* redr = (float*)(smem + T_SCR);    // [128][4]
        float* redc = redr + 512;                // [256][2]

        // Row mins: flush every tile (16 shfl)
#pragma unroll
        for (int mt = 0; mt < 4; mt++) {
#pragma unroll
            for (int off = 1; off <= 2; off <<= 1) {
                rmin0[mt] = fminf(rmin0[mt], __shfl_xor_sync(0xFFFFFFFFu, rmin0[mt], off));
                rmin1[mt] = fminf(rmin1[mt], __shfl_xor_sync(0xFFFFFFFFu, rmin1[mt], off));
            }
        }
        if (t == 0) {
#pragma unroll
            for (int mt = 0; mt < 4; mt++) {
                int r = wn * 64 + mt * 16 + g;
                redr[r * 4 + wm] = rmin0[mt];
                redr[(r + 8) * 4 + wm] = rmin1[mt];
            }
        }

        // Col mins: flush at column end only
        const bool colend = (tt == t1 - 1) || ((tt & 31) == 31);
        if (colend) {
            float c0v[8], c1v[8];
#pragma unroll
            for (int nt = 0; nt < 8; nt++) {
                c0v[nt] = cmin0[nt]; c1v[nt] = cmin1[nt];
#pragma unroll
                for (int off = 4; off <= 16; off <<= 1) {
                    c0v[nt] = fminf(c0v[nt], __shfl_xor_sync(0xFFFFFFFFu, c0v[nt], off));
                    c1v[nt] = fminf(c1v[nt], __shfl_xor_sync(0xFFFFFFFFu, c1v[nt], off));
                }
            }
            if (g == 0) {
#pragma unroll
                for (int nt = 0; nt < 8; nt++) {
                    int c = wm * 64 + nt * 8 + 2 * t;
                    redc[c * 2 + wn] = c0v[nt];
                    redc[(c + 1) * 2 + wn] = c1v[nt];
                }
            }
        }
        __syncthreads();

        if (tid < 128) {
            float rv = fminf(fminf(redr[tid * 4], redr[tid * 4 + 1]),
                             fminf(redr[tid * 4 + 2], redr[tid * 4 + 3]));
            rv = fmaxf(rv, 0.0f);
            atomicMin((int*)&g_rowmin[(size_t)b * NN + n0 + tid], __float_as_int(rv));
        }
        if (colend) {
            float cv = fminf(redc[tid * 2], redc[tid * 2 + 1]);
            cv = fmaxf(cv, 0.0f);
            atomicMin((int*)&g_colmin[(size_t)b * MM + m0 + tid], __float_as_int(cv));
        }
        __syncthreads();   // buffers/scratch safe for next iteration's TMA issue
    }
}

// ================= cp.async fallback (R10 kernel, proven 113us) =================
__global__ void __launch_bounds__(256, 1)
chamfer_cp_kernel() {
    extern __shared__ char smem[];
    uint32_t sbase = smem_u32(smem);

    const int tid  = threadIdx.x;
    const int lane = tid & 31;
    const int w    = tid >> 5;
    const int g    = lane >> 2;
    const int t    = lane & 3;
    const int wn   = w >> 2;
    const int wm   = w & 3;

    const int chunk = (TT_TOTAL + gridDim.x - 1) / gridDim.x;
    const int t0 = blockIdx.x * chunk;
    const int t1 = min(t0 + chunk, TT_TOTAL);
    if (t0 >= TT_TOTAL) return;

    const int arow = lane & 15;
    const int akc  = lane >> 4;
    const int brow = ((lane >> 4) << 3) + (lane & 7);
    const int bkc  = (lane >> 3) & 1;

    auto stageA = [&](int tt) {
        int cc = tt >> 5, b = cc >> 4;
        int n0 = (tt & 31) * TN;
        uint32_t abuf = sbase + AOFF + (tt & 1) * ABUF;
        const __half* xb = g_xh + ((size_t)b * NN + n0) * CC;
#pragma unroll
        for (int p = 0; p < 8; p++) {
            int c = p * 256 + tid;
            int s = c >> 10;
            int r = (c & 1023) >> 3, col = c & 7;
            cp16(abuf + s * ASL + r * RSB + col * 16,
                 xb + (size_t)r * CC + s * 64 + col * 8);
        }
    };
    auto stageB = [&](int cc) {
        int b = cc >> 4, m0 = (cc & 15) * TM;
        const __half* yb = g_yh + ((size_t)b * MM + m0) * CC;
#pragma unroll
        for (int p = 0; p < 16; p++) {
            int c = p * 256 + tid;
            int s = c >> 11;
            int r = (c & 2047) >> 3, col = c & 7;
            cp16(sbase + s * BSL + r * RSB + col * 16,
                 yb + (size_t)r * CC + s * 64 + col * 8);
        }
    };

    float cmin0[8], cmin1[8];
    float y2a[8], y2b[8];

    for (int tt = t0; tt < t1; tt++) {
        const int cc = tt >> 5;
        const int b  = cc >> 4;
        const int n0 = (tt & 31) * TN;
        const int m0 = (cc & 15) * TM;

        const bool colstart = (tt == t0) || ((tt & 31) == 0);
        if (colstart) {
            stageB(cc);
            stageA(tt);
            cp_commit();
#pragma unroll
            for (int q = 0; q < 8; q++) { cmin0[q] = FINF; cmin1[q] = FINF; }
#pragma unroll
            for (int nt = 0; nt < 8; nt++) {
                int c0 = m0 + wm * 64 + nt * 8 + 2 * t;
                y2a[nt] = g_y2[(size_t)b * MM + c0];
                y2b[nt] = g_y2[(size_t)b * MM + c0 + 1];
            }
        }
        const bool pref = (tt + 1 < t1) && (((tt + 1) & 31) != 0);
        if (pref) { stageA(tt + 1); cp_commit(); }
        if (pref) cp_wait<1>(); else cp_wait<0>();
        __syncthreads();

        const uint32_t abase = sbase + AOFF + (tt & 1) * ABUF;

        float acc[4][8][4];
#pragma unroll
        for (int mt = 0; mt < 4; mt++)
#pragma unroll
            for (int nt = 0; nt < 8; nt++)
#pragma unroll
                for (int c = 0; c < 4; c++)
                    acc[mt][nt][c] = 0.0f;

#pragma unroll
        for (int s = 0; s < 2; s++) {
            uint32_t abuf = abase + s * ASL;
            uint32_t bbuf = sbase + s * BSL;
#pragma unroll
            for (int ks = 0; ks < 4; ks++) {
                uint32_t a[4][4], bf[8][2];
#pragma unroll
                for (int mt = 0; mt < 4; mt++)
                    ldsm4(a[mt][0], a[mt][1], a[mt][2], a[mt][3],
                          abuf + (wn * 64 + mt * 16 + arow) * RSB + ks * 32 + akc * 16);
#pragma unroll
                for (int p = 0; p < 4; p++) {
                    uint32_t r0, r1, r2, r3;
                    ldsm4(r0, r1, r2, r3,
                          bbuf + (wm * 64 + p * 16 + brow) * RSB + ks * 32 + bkc * 16);
                    bf[2 * p][0] = r0; bf[2 * p][1] = r1;
                    bf[2 * p + 1][0] = r2; bf[2 * p + 1][1] = r3;
                }
#pragma unroll
                for (int mt = 0; mt < 4; mt++)
#pragma unroll
                    for (int nt = 0; nt < 8; nt++)
                        mma_f16(acc[mt][nt][0], acc[mt][nt][1], acc[mt][nt][2], acc[mt][nt][3],
                                a[mt][0], a[mt][1], a[mt][2], a[mt][3],
                                bf[nt][0], bf[nt][1]);
            }
        }

        float rmin0[4], rmin1[4];
#pragma unroll
        for (int mt = 0; mt < 4; mt++) {
            int r0 = n0 + wn * 64 + mt * 16 + g;
            float x2a = g_x2[(size_t)b * NN + r0];
            float x2b = g_x2[(size_t)b * NN + r0 + 8];
            float ra = FINF, rb = FINF;
#pragma unroll
            for (int nt = 0; nt < 8; nt++) {
                float d00 = x2a + y2a[nt] - 2.0f * acc[mt][nt][0];
                float d01 = x2a + y2b[nt] - 2.0f * acc[mt][nt][1];
                float d10 = x2b + y2a[nt] - 2.0f * acc[mt][nt][2];
                float d11 = x2b + y2b[nt] - 2.0f * acc[mt][nt][3];
                ra = fminf(ra, fminf(d00, d01));
                rb = fminf(rb, fminf(d10, d11));
                cmin0[nt] = fminf(cmin0[nt], fminf(d00, d10));
                cmin1[nt] = fminf(cmin1[nt], fminf(d01, d11));
            }
            rmin0[mt] = ra;
            rmin1[mt] = rb;
        }

        float* redr = (float*)(smem + SCR);
        float* redc = redr + 512;

#pragma unroll
        for (int mt = 0; mt < 4; mt++) {
#pragma unroll
            for (int off = 1; off <= 2; off <<= 1) {
                rmin0[mt] = fminf(rmin0[mt], __shfl_xor_sync(0xFFFFFFFFu, rmin0[mt], off));
                rmin1[mt] = fminf(rmin1[mt], __shfl_xor_sync(0xFFFFFFFFu, rmin1[mt], off));
            }
        }
        if (t == 0) {
#pragma unroll
            for (int mt = 0; mt < 4; mt++) {
                int r = wn * 64 + mt * 16 + g;
                redr[r * 4 + wm] = rmin0[mt];
                redr[(r + 8) * 4 + wm] = rmin1[mt];
            }
        }

        const bool colend = (tt == t1 - 1) || ((tt & 31) == 31);
        if (colend) {
            float c0v[8], c1v[8];
#pragma unroll
            for (int nt = 0; nt < 8; nt++) {
                c0v[nt] = cmin0[nt]; c1v[nt] = cmin1[nt];
#pragma unroll
                for (int off = 4; off <= 16; off <<= 1) {
                    c0v[nt] = fminf(c0v[nt], __shfl_xor_sync(0xFFFFFFFFu, c0v[nt], off));
                    c1v[nt] = fminf(c1v[nt], __shfl_xor_sync(0xFFFFFFFFu, c1v[nt], off));
                }
            }
            if (g == 0) {
#pragma unroll
                for (int nt = 0; nt < 8; nt++) {
                    int c = wm * 64 + nt * 8 + 2 * t;
                    redc[c * 2 + wn] = c0v[nt];
                    redc[(c + 1) * 2 + wn] = c1v[nt];
                }
            }
        }
        __syncthreads();

        if (tid < 128) {
            float rv = fminf(fminf(redr[tid * 4], redr[tid * 4 + 1]),
                             fminf(redr[tid * 4 + 2], redr[tid * 4 + 3]));
            rv = fmaxf(rv, 0.0f);
            atomicMin((int*)&g_rowmin[(size_t)b * NN + n0 + tid], __float_as_int(rv));
        }
        if (colend) {
            float cv = fminf(redc[tid * 2], redc[tid * 2 + 1]);
            cv = fmaxf(cv, 0.0f);
            atomicMin((int*)&g_colmin[(size_t)b * MM + m0 + tid], __float_as_int(cv));
        }
        __syncthreads();
    }
}

// Weighted reduction; last block writes the output.
__global__ void partial_final_kernel(const float* __restrict__ w1,
                                     const float* __restrict__ w2,
                                     float* __restrict__ out) {
    __shared__ double sh[256];
    int tid = threadIdx.x;
    int gid = blockIdx.x * 256 + tid;
    int stride = gridDim.x * 256;
    double s = 0.0;
    for (int i = gid; i < BB * NN; i += stride)
        s += (double)w1[i] * sqrtf(g_rowmin[i]);
    for (int i = gid; i < BB * MM; i += stride)
        s += (double)w2[i] * sqrtf(g_colmin[i]);
    sh[tid] = s;
    __syncthreads();
    for (int off = 128; off > 0; off >>= 1) {
        if (tid < off) sh[tid] += sh[tid + off];
        __syncthreads();
    }
    if (tid == 0) {
        atomicAdd(&g_acc, sh[0]);
        __threadfence();
        int done = atomicAdd(&g_done, 1);
        if (done == (int)gridDim.x - 1) {
            double total = atomicAdd(&g_acc, 0.0);
            out[0] = (float)(total * 0.5);
            g_done = 0;
        }
    }
}

typedef CUresult (*EncodeFn)(CUtensorMap*, CUtensorMapDataType, cuuint32_t, void*,
                             const cuuint64_t*, const cuuint64_t*, const cuuint32_t*,
                             const cuuint32_t*, CUtensorMapInterleave, CUtensorMapSwizzle,
                             CUtensorMapL2promotion, CUtensorMapFloatOOBfill);

extern "C" void kernel_launch(void* const* d_in, const int* in_sizes, int n_in,
                              void* d_out, int out_size) {
    const float* set1 = (const float*)d_in[0];
    const float* set2 = (const float*)d_in[1];
    const float* w1   = (const float*)d_in[2];
    const float* w2   = (const float*)d_in[3];
    float* out = (float*)d_out;

    int nsm = 148;
    cudaDeviceGetAttribute(&nsm, cudaDevAttrMultiProcessorCount, 0);

    dim3 ngrid((BB * NN) / 8, 2, 1);
    convert_norms_kernel<<<ngrid, 256>>>(set1, set2);

    // Try to build TMA tensor maps via runtime-resolved driver entry point.
    bool tma_ok = false;
    CUtensorMap tmX, tmY;
    {
        EncodeFn enc = nullptr;
        cudaDriverEntryPointQueryResult qr;
        if (cudaGetDriverEntryPoint("cuTensorMapEncodeTiled", (void**)&enc,
                                    cudaEnableDefault, &qr) == cudaSuccess && enc) {
            void *xaddr = nullptr, *yaddr = nullptr;
            cudaGetSymbolAddress(&xaddr, g_xh);
            cudaGetSymbolAddress(&yaddr, g_yh);
            if (xaddr && yaddr) {
                cuuint64_t dims[2] = {128, (cuuint64_t)BB * NN};
                cuuint64_t strides[1] = {CC * 2};
                cuuint32_t boxX[2] = {64, TN}, boxY[2] = {64, TM}, es[2] = {1, 1};
                CUresult r1 = enc(&tmX, CU_TENSOR_MAP_DATA_TYPE_UINT16, 2, xaddr,
                                  dims, strides, boxX, es,
                                  CU_TENSOR_MAP_INTERLEAVE_NONE, CU_TENSOR_MAP_SWIZZLE_128B,
                                  CU_TENSOR_MAP_L2_PROMOTION_L2_128B,
                                  CU_TENSOR_MAP_FLOAT_OOB_FILL_NONE);
                CUresult r2 = enc(&tmY, CU_TENSOR_MAP_DATA_TYPE_UINT16, 2, yaddr,
                                  dims, strides, boxY, es,
                                  CU_TENSOR_MAP_INTERLEAVE_NONE, CU_TENSOR_MAP_SWIZZLE_128B,
                                  CU_TENSOR_MAP_L2_PROMOTION_L2_128B,
                                  CU_TENSOR_MAP_FLOAT_OOB_FILL_NONE);
                tma_ok = (r1 == CUDA_SUCCESS) && (r2 == CUDA_SUCCESS);
            }
        }
    }

    if (tma_ok) {
        cudaFuncSetAttribute(chamfer_tma_kernel,
                             cudaFuncAttributeMaxDynamicSharedMemorySize, T_SMEM);
        chamfer_tma_kernel<<<nsm, 256, T_SMEM>>>(tmX, tmY);
    } else {
        cudaFuncSetAttribute(chamfer_cp_kernel,
                             cudaFuncAttributeMaxDynamicSharedMemorySize, SMEM_BYTES);
        chamfer_cp_kernel<<<nsm, 256, SMEM_BYTES>>>();
    }

    partial_final_kernel<<<64, 256>>>(w1, w2, out);
}

// round 13
// speedup vs baseline: 8.4857x; 1.0379x over previous
#include <cuda_runtime.h>
#include <cuda.h>
#include <cuda_fp16.h>
#include <math.h>
#include <stdint.h>

// Problem shape (fixed by the dataset)
#define BB 8
#define NN 4096
#define MM 4096
#define CC 128

#define FINF __int_as_float(0x7F800000)

// ---- TMA kernel (2 CTA/SM): tile 128x128, 128 threads ----
#define T2N 128
#define T2M 128
#define T2_TOTAL 8192          // 32 n-tiles * 32 m-tiles * 8 batches
#define T2_BSL 16384           // B K-slice (128 rows * 128B)
#define T2_ASL 16384           // A K-slice
#define T2_AOFF (2 * T2_BSL)   // 32768
#define T2_ABUF (2 * T2_ASL)   // 32768 per A buffer
#define T2_SCR (T2_AOFF + 2 * T2_ABUF)  // 98304 (2 parity scratch bufs x 2KB)
#define T2_MBAR (T2_SCR + 4096)         // 102400
#define T2_SMEM (T2_MBAR + 64)          // 102464 -> 2 CTAs/SM

// ---- cp.async fallback (R10, proven 113us) ----
#define TN 128
#define TM 256
#define TT_TOTAL 4096
#define RSB 144
#define ASL 18432
#define BSL 36864
#define ABUF (2 * ASL)
#define BBUF (2 * BSL)
#define AOFF BBUF
#define SCR  (AOFF + 2 * ABUF)
#define SMEM_BYTES (SCR + 4096)

// Scratch (no allocations allowed in kernel_launch)
__device__ float  g_rowmin[BB * NN];
__device__ float  g_colmin[BB * MM];
__device__ float  g_x2[BB * NN];
__device__ float  g_y2[BB * MM];
__device__ double g_acc;
__device__ int    g_done = 0;
__device__ __half g_xh[BB * NN * CC];
__device__ __half g_yh[BB * MM * CC];

// One warp per point: fp32 -> fp16 + norm of the ROUNDED values; fused init.
__global__ void convert_norms_kernel(const float* __restrict__ X, const float* __restrict__ Y) {
    int gwarp = (blockIdx.x * blockDim.x + threadIdx.x) >> 5;
    int lane = threadIdx.x & 31;

    if (threadIdx.x < 8) {
        int idx = blockIdx.x * 8 + threadIdx.x;
        if (blockIdx.y) g_colmin[idx] = FINF; else g_rowmin[idx] = FINF;
        if (idx == 0 && blockIdx.y == 0) { g_acc = 0.0; g_done = 0; }
    }

    const float* src = blockIdx.y ? Y : X;
    __half* dsth = blockIdx.y ? g_yh : g_xh;
    float* dst2 = blockIdx.y ? g_y2 : g_x2;
    if (gwarp >= BB * NN) return;

    float4 v = ((const float4*)(src + (size_t)gwarp * CC))[lane];
    __half2 h0 = __floats2half2_rn(v.x, v.y);
    __half2 h1 = __floats2half2_rn(v.z, v.w);
    uint2 st;
    st.x = *(const unsigned*)&h0;
    st.y = *(const unsigned*)&h1;
    ((uint2*)(dsth + (size_t)gwarp * CC))[lane] = st;

    float2 b0 = __half22float2(h0), b1 = __half22float2(h1);
    float s = b0.x * b0.x + b0.y * b0.y + b1.x * b1.x + b1.y * b1.y;
#pragma unroll
    for (int off = 16; off > 0; off >>= 1)
        s += __shfl_xor_sync(0xFFFFFFFFu, s, off);
    if (lane == 0) dst2[gwarp] = s;
}

// ---------------- PTX helpers ----------------
__device__ __forceinline__ uint32_t smem_u32(const void* p) {
    return (uint32_t)__cvta_generic_to_shared(p);
}
__device__ __forceinline__ void cp16(uint32_t saddr, const void* gaddr) {
    asm volatile("cp.async.cg.shared.global [%0], [%1], 16;\n" :: "r"(saddr), "l"(gaddr));
}
__device__ __forceinline__ void cp_commit() { asm volatile("cp.async.commit_group;\n"); }
template <int N>
__device__ __forceinline__ void cp_wait() { asm volatile("cp.async.wait_group %0;\n" :: "n"(N)); }

__device__ __forceinline__ void ldsm4(uint32_t& r0, uint32_t& r1, uint32_t& r2, uint32_t& r3,
                                      uint32_t addr) {
    asm volatile("ldmatrix.sync.aligned.m8n8.x4.shared.b16 {%0,%1,%2,%3}, [%4];"
                 : "=r"(r0), "=r"(r1), "=r"(r2), "=r"(r3) : "r"(addr));
}
__device__ __forceinline__ void mma_f16(float& c0, float& c1, float& c2, float& c3,
                                        uint32_t a0, uint32_t a1, uint32_t a2, uint32_t a3,
                                        uint32_t b0, uint32_t b1) {
    asm volatile(
        "mma.sync.aligned.m16n8k16.row.col.f32.f16.f16.f32 "
        "{%0,%1,%2,%3}, {%4,%5,%6,%7}, {%8,%9}, {%0,%1,%2,%3};"
        : "+f"(c0), "+f"(c1), "+f"(c2), "+f"(c3)
        : "r"(a0), "r"(a1), "r"(a2), "r"(a3), "r"(b0), "r"(b1));
}
__device__ __forceinline__ void mbar_init(uint32_t a, uint32_t cnt) {
    asm volatile("mbarrier.init.shared.b64 [%0], %1;" :: "r"(a), "r"(cnt) : "memory");
}
__device__ __forceinline__ void mbar_expect(uint32_t a, uint32_t bytes) {
    asm volatile("mbarrier.arrive.expect_tx.shared.b64 _, [%0], %1;" :: "r"(a), "r"(bytes) : "memory");
}
__device__ __forceinline__ void mbar_wait(uint32_t a, uint32_t parity) {
    asm volatile(
        "{\n\t.reg .pred P1;\n\t"
        "WL%=:\n\t"
        "mbarrier.try_wait.parity.acquire.cta.shared::cta.b64 P1, [%0], %1, 0x989680;\n\t"
        "@P1 bra.uni WD%=;\n\t"
        "bra.uni WL%=;\n\t"
        "WD%=:\n\t}"
        :: "r"(a), "r"(parity) : "memory");
}
__device__ __forceinline__ void tma2d(uint32_t dst, const void* tmap, int x, int y, uint32_t mbar) {
    asm volatile(
        "cp.async.bulk.tensor.2d.shared::cta.global.tile.mbarrier::complete_tx::bytes "
        "[%0], [%1, {%2, %3}], [%4];"
        :: "r"(dst), "l"(tmap), "r"(x), "r"(y), "r"(mbar) : "memory");
}

// ================= TMA persistent kernel, 2 CTA/SM =================
// Tile tt: n-tile = tt&31 (fastest), column cc = tt>>5; m-tile = cc&31, b = cc>>5.
// B (128 pts) resident per column; A double-buffered via TMA + mbarrier.
// 128 threads = 4 warps in 2x2; warp tile 64x64 (mt=4, nt=8).
__global__ void __launch_bounds__(128)
chamfer_tma_kernel(const __grid_constant__ CUtensorMap tmX,
                   const __grid_constant__ CUtensorMap tmY) {
    extern __shared__ __align__(1024) char smem[];
    uint32_t sbase = smem_u32(smem);

    const int tid  = threadIdx.x;
    const int lane = tid & 31;
    const int w    = tid >> 5;        // 0..3
    const int g    = lane >> 2;
    const int t    = lane & 3;
    const int wn   = w >> 1;          // 0..1 -> row half
    const int wm   = w & 1;           // 0..1 -> col half

    const int chunk = (T2_TOTAL + gridDim.x - 1) / gridDim.x;
    const int t0 = blockIdx.x * chunk;
    const int t1 = min(t0 + chunk, T2_TOTAL);
    if (t0 >= T2_TOTAL) return;

    const int arow = lane & 15;
    const int akc  = lane >> 4;
    const int brow = ((lane >> 4) << 3) + (lane & 7);
    const int bkc  = (lane >> 3) & 1;

    if (tid == 0) { mbar_init(sbase + T2_MBAR, 1); mbar_init(sbase + T2_MBAR + 8, 1); }
    __syncthreads();

    int ph[2] = {0, 0};
    float cmin0[8], cmin1[8];
    float y2a[8], y2b[8];

    for (int tt = t0; tt < t1; tt++) {
        const int cc = tt >> 5;
        const int b  = cc >> 5;
        const int n0 = (tt & 31) * T2N;
        const int m0 = (cc & 31) * T2M;
        const int p  = tt & 1;

        const bool colstart = (tt == t0) || ((tt & 31) == 0);
        if (colstart) {
            if (tid == 0) {
                mbar_expect(sbase + T2_MBAR + p * 8, 2 * T2_BSL + 2 * T2_ASL);
                tma2d(sbase,           &tmY, 0,  b * MM + m0, sbase + T2_MBAR + p * 8);
                tma2d(sbase + T2_BSL,  &tmY, 64, b * MM + m0, sbase + T2_MBAR + p * 8);
                uint32_t abuf = sbase + T2_AOFF + p * T2_ABUF;
                tma2d(abuf,           &tmX, 0,  b * NN + n0, sbase + T2_MBAR + p * 8);
                tma2d(abuf + T2_ASL,  &tmX, 64, b * NN + n0, sbase + T2_MBAR + p * 8);
            }
#pragma unroll
            for (int q = 0; q < 8; q++) { cmin0[q] = FINF; cmin1[q] = FINF; }
#pragma unroll
            for (int nt = 0; nt < 8; nt++) {
                int c0 = m0 + wm * 64 + nt * 8 + 2 * t;
                y2a[nt] = g_y2[(size_t)b * MM + c0];
                y2b[nt] = g_y2[(size_t)b * MM + c0 + 1];
            }
        }
        // prefetch next A within the column
        if (tid == 0 && (tt + 1 < t1) && (((tt + 1) & 31) != 0)) {
            int pn = p ^ 1;
            int nn0 = ((tt + 1) & 31) * T2N;
            uint32_t abuf = sbase + T2_AOFF + pn * T2_ABUF;
            mbar_expect(sbase + T2_MBAR + pn * 8, 2 * T2_ASL);
            tma2d(abuf,          &tmX, 0,  b * NN + nn0, sbase + T2_MBAR + pn * 8);
            tma2d(abuf + T2_ASL, &tmX, 64, b * NN + nn0, sbase + T2_MBAR + pn * 8);
        }

        mbar_wait(sbase + T2_MBAR + p * 8, ph[p]);
        ph[p] ^= 1;

        const uint32_t abase = sbase + T2_AOFF + p * T2_ABUF;

        float acc[4][8][4];
#pragma unroll
        for (int mt = 0; mt < 4; mt++)
#pragma unroll
            for (int nt = 0; nt < 8; nt++)
#pragma unroll
                for (int c = 0; c < 4; c++)
                    acc[mt][nt][c] = 0.0f;

#pragma unroll
        for (int s = 0; s < 2; s++) {
            uint32_t abuf = abase + s * T2_ASL;
            uint32_t bbuf = sbase + s * T2_BSL;
#pragma unroll
            for (int ks = 0; ks < 4; ks++) {
                uint32_t a[4][4], bf[8][2];
#pragma unroll
                for (int mt = 0; mt < 4; mt++) {
                    int r = wn * 64 + mt * 16 + arow;
                    ldsm4(a[mt][0], a[mt][1], a[mt][2], a[mt][3],
                          abuf + r * 128 + (((ks * 2 + akc) ^ (r & 7)) << 4));
                }
#pragma unroll
                for (int pp = 0; pp < 4; pp++) {
                    int r = wm * 64 + pp * 16 + brow;
                    uint32_t r0, r1, r2, r3;
                    ldsm4(r0, r1, r2, r3,
                          bbuf + r * 128 + (((ks * 2 + bkc) ^ (r & 7)) << 4));
                    bf[2 * pp][0] = r0; bf[2 * pp][1] = r1;
                    bf[2 * pp + 1][0] = r2; bf[2 * pp + 1][1] = r3;
                }
#pragma unroll
                for (int mt = 0; mt < 4; mt++)
#pragma unroll
                    for (int nt = 0; nt < 8; nt++)
                        mma_f16(acc[mt][nt][0], acc[mt][nt][1], acc[mt][nt][2], acc[mt][nt][3],
                                a[mt][0], a[mt][1], a[mt][2], a[mt][3],
                                bf[nt][0], bf[nt][1]);
            }
        }

        // Epilogue. C frag: c0=(g,2t) c1=(g,2t+1) c2=(g+8,2t) c3=(g+8,2t+1).
        float rmin0[4], rmin1[4];
#pragma unroll
        for (int mt = 0; mt < 4; mt++) {
            int r0 = n0 + wn * 64 + mt * 16 + g;
            float x2a = g_x2[(size_t)b * NN + r0];
            float x2b = g_x2[(size_t)b * NN + r0 + 8];
            float ra = FINF, rb = FINF;
#pragma unroll
            for (int nt = 0; nt < 8; nt++) {
                float d00 = x2a + y2a[nt] - 2.0f * acc[mt][nt][0];
                float d01 = x2a + y2b[nt] - 2.0f * acc[mt][nt][1];
                float d10 = x2b + y2a[nt] - 2.0f * acc[mt][nt][2];
                float d11 = x2b + y2b[nt] - 2.0f * acc[mt][nt][3];
                ra = fminf(ra, fminf(d00, d01));
                rb = fminf(rb, fminf(d10, d11));
                cmin0[nt] = fminf(cmin0[nt], fminf(d00, d10));
                cmin1[nt] = fminf(cmin1[nt], fminf(d01, d11));
            }
            rmin0[mt] = ra;
            rmin1[mt] = rb;
        }

        // parity-doubled scratch: one __syncthreads per tile
        float* redr = (float*)(smem + T2_SCR + (tt & 1) * 2048);  // [128][2]
        float* redc = redr + 256;                                 // [128][2]

        // Row mins: flush every tile (16 shfl)
#pragma unroll
        for (int mt = 0; mt < 4; mt++) {
#pragma unroll
            for (int off = 1; off <= 2; off <<= 1) {
                rmin0[mt] = fminf(rmin0[mt], __shfl_xor_sync(0xFFFFFFFFu, rmin0[mt], off));
                rmin1[mt] = fminf(rmin1[mt], __shfl_xor_sync(0xFFFFFFFFu, rmin1[mt], off));
            }
        }
        if (t == 0) {
#pragma unroll
            for (int mt = 0; mt < 4; mt++) {
                int r = wn * 64 + mt * 16 + g;
                redr[r * 2 + wm] = rmin0[mt];
                redr[(r + 8) * 2 + wm] = rmin1[mt];
            }
        }

        // Col mins: flush at column end only
        const bool colend = (tt == t1 - 1) || ((tt & 31) == 31);
        if (colend) {
            float c0v[8], c1v[8];
#pragma unroll
            for (int nt = 0; nt < 8; nt++) {
                c0v[nt] = cmin0[nt]; c1v[nt] = cmin1[nt];
#pragma unroll
                for (int off = 4; off <= 16; off <<= 1) {
                    c0v[nt] = fminf(c0v[nt], __shfl_xor_sync(0xFFFFFFFFu, c0v[nt], off));
                    c1v[nt] = fminf(c1v[nt], __shfl_xor_sync(0xFFFFFFFFu, c1v[nt], off));
                }
            }
            if (g == 0) {
#pragma unroll
                for (int nt = 0; nt < 8; nt++) {
                    int c = wm * 64 + nt * 8 + 2 * t;
                    redc[c * 2 + wn] = c0v[nt];
                    redc[(c + 1) * 2 + wn] = c1v[nt];
                }
            }
        }
        __syncthreads();

        {
            float rv = fminf(redr[tid * 2], redr[tid * 2 + 1]);
            rv = fmaxf(rv, 0.0f);
            atomicMin((int*)&g_rowmin[(size_t)b * NN + n0 + tid], __float_as_int(rv));
        }
        if (colend) {
            float cv = fminf(redc[tid * 2], redc[tid * 2 + 1]);
            cv = fmaxf(cv, 0.0f);
            atomicMin((int*)&g_colmin[(size_t)b * MM + m0 + tid], __float_as_int(cv));
        }
        // no trailing sync: scratch parity + mbarrier phases guard reuse
    }
}

// ================= cp.async fallback (R10 kernel, proven 113us) =================
__global__ void __launch_bounds__(256, 1)
chamfer_cp_kernel() {
    extern __shared__ char smem[];
    uint32_t sbase = smem_u32(smem);

    const int tid  = threadIdx.x;
    const int lane = tid & 31;
    const int w    = tid >> 5;
    const int g    = lane >> 2;
    const int t    = lane & 3;
    const int wn   = w >> 2;
    const int wm   = w & 3;

    const int chunk = (TT_TOTAL + gridDim.x - 1) / gridDim.x;
    const int t0 = blockIdx.x * chunk;
    const int t1 = min(t0 + chunk, TT_TOTAL);
    if (t0 >= TT_TOTAL) return;

    const int arow = lane & 15;
    const int akc  = lane >> 4;
    const int brow = ((lane >> 4) << 3) + (lane & 7);
    const int bkc  = (lane >> 3) & 1;

    auto stageA = [&](int tt) {
        int cc = tt >> 5, b = cc >> 4;
        int n0 = (tt & 31) * TN;
        uint32_t abuf = sbase + AOFF + (tt & 1) * ABUF;
        const __half* xb = g_xh + ((size_t)b * NN + n0) * CC;
#pragma unroll
        for (int p = 0; p < 8; p++) {
            int c = p * 256 + tid;
            int s = c >> 10;
            int r = (c & 1023) >> 3, col = c & 7;
            cp16(abuf + s * ASL + r * RSB + col * 16,
                 xb + (size_t)r * CC + s * 64 + col * 8);
        }
    };
    auto stageB = [&](int cc) {
        int b = cc >> 4, m0 = (cc & 15) * TM;
        const __half* yb = g_yh + ((size_t)b * MM + m0) * CC;
#pragma unroll
        for (int p = 0; p < 16; p++) {
            int c = p * 256 + tid;
            int s = c >> 11;
            int r = (c & 2047) >> 3, col = c & 7;
            cp16(sbase + s * BSL + r * RSB + col * 16,
                 yb + (size_t)r * CC + s * 64 + col * 8);
        }
    };

    float cmin0[8], cmin1[8];
    float y2a[8], y2b[8];

    for (int tt = t0; tt < t1; tt++) {
        const int cc = tt >> 5;
        const int b  = cc >> 4;
        const int n0 = (tt & 31) * TN;
        const int m0 = (cc & 15) * TM;

        const bool colstart = (tt == t0) || ((tt & 31) == 0);
        if (colstart) {
            stageB(cc);
            stageA(tt);
            cp_commit();
#pragma unroll
            for (int q = 0; q < 8; q++) { cmin0[q] = FINF; cmin1[q] = FINF; }
#pragma unroll
            for (int nt = 0; nt < 8; nt++) {
                int c0 = m0 + wm * 64 + nt * 8 + 2 * t;
                y2a[nt] = g_y2[(size_t)b * MM + c0];
                y2b[nt] = g_y2[(size_t)b * MM + c0 + 1];
            }
        }
        const bool pref = (tt + 1 < t1) && (((tt + 1) & 31) != 0);
        if (pref) { stageA(tt + 1); cp_commit(); }
        if (pref) cp_wait<1>(); else cp_wait<0>();
        __syncthreads();

        const uint32_t abase = sbase + AOFF + (tt & 1) * ABUF;

        float acc[4][8][4];
#pragma unroll
        for (int mt = 0; mt < 4; mt++)
#pragma unroll
            for (int nt = 0; nt < 8; nt++)
#pragma unroll
                for (int c = 0; c < 4; c++)
                    acc[mt][nt][c] = 0.0f;

#pragma unroll
        for (int s = 0; s < 2; s++) {
            uint32_t abuf = abase + s * ASL;
            uint32_t bbuf = sbase + s * BSL;
#pragma unroll
            for (int ks = 0; ks < 4; ks++) {
                uint32_t a[4][4], bf[8][2];
#pragma unroll
                for (int mt = 0; mt < 4; mt++)
                    ldsm4(a[mt][0], a[mt][1], a[mt][2], a[mt][3],
                          abuf + (wn * 64 + mt * 16 + arow) * RSB + ks * 32 + akc * 16);
#pragma unroll
                for (int p = 0; p < 4; p++) {
                    uint32_t r0, r1, r2, r3;
                    ldsm4(r0, r1, r2, r3,
                          bbuf + (wm * 64 + p * 16 + brow) * RSB + ks * 32 + bkc * 16);
                    bf[2 * p][0] = r0; bf[2 * p][1] = r1;
                    bf[2 * p + 1][0] = r2; bf[2 * p + 1][1] = r3;
                }
#pragma unroll
                for (int mt = 0; mt < 4; mt++)
#pragma unroll
                    for (int nt = 0; nt < 8; nt++)
                        mma_f16(acc[mt][nt][0], acc[mt][nt][1], acc[mt][nt][2], acc[mt][nt][3],
                                a[mt][0], a[mt][1], a[mt][2], a[mt][3],
                                bf[nt][0], bf[nt][1]);
            }
        }

        float rmin0[4], rmin1[4];
#pragma unroll
        for (int mt = 0; mt < 4; mt++) {
            int r0 = n0 + wn * 64 + mt * 16 + g;
            float x2a = g_x2[(size_t)b * NN + r0];
            float x2b = g_x2[(size_t)b * NN + r0 + 8];
            float ra = FINF, rb = FINF;
#pragma unroll
            for (int nt = 0; nt < 8; nt++) {
                float d00 = x2a + y2a[nt] - 2.0f * acc[mt][nt][0];
                float d01 = x2a + y2b[nt] - 2.0f * acc[mt][nt][1];
                float d10 = x2b + y2a[nt] - 2.0f * acc[mt][nt][2];
                float d11 = x2b + y2b[nt] - 2.0f * acc[mt][nt][3];
                ra = fminf(ra, fminf(d00, d01));
                rb = fminf(rb, fminf(d10, d11));
                cmin0[nt] = fminf(cmin0[nt], fminf(d00, d10));
                cmin1[nt] = fminf(cmin1[nt], fminf(d01, d11));
            }
            rmin0[mt] = ra;
            rmin1[mt] = rb;
        }

        float* redr = (float*)(smem + SCR);
        float* redc = redr + 512;

#pragma unroll
        for (int mt = 0; mt < 4; mt++) {
#pragma unroll
            for (int off = 1; off <= 2; off <<= 1) {
                rmin0[mt] = fminf(rmin0[mt], __shfl_xor_sync(0xFFFFFFFFu, rmin0[mt], off));
                rmin1[mt] = fminf(rmin1[mt], __shfl_xor_sync(0xFFFFFFFFu, rmin1[mt], off));
            }
        }
        if (t == 0) {
#pragma unroll
            for (int mt = 0; mt < 4; mt++) {
                int r = wn * 64 + mt * 16 + g;
                redr[r * 4 + wm] = rmin0[mt];
                redr[(r + 8) * 4 + wm] = rmin1[mt];
            }
        }

        const bool colend = (tt == t1 - 1) || ((tt & 31) == 31);
        if (colend) {
            float c0v[8], c1v[8];
#pragma unroll
            for (int nt = 0; nt < 8; nt++) {
                c0v[nt] = cmin0[nt]; c1v[nt] = cmin1[nt];
#pragma unroll
                for (int off = 4; off <= 16; off <<= 1) {
                    c0v[nt] = fminf(c0v[nt], __shfl_xor_sync(0xFFFFFFFFu, c0v[nt], off));
                    c1v[nt] = fminf(c1v[nt], __shfl_xor_sync(0xFFFFFFFFu, c1v[nt], off));
                }
            }
            if (g == 0) {
#pragma unroll
                for (int nt = 0; nt < 8; nt++) {
                    int c = wm * 64 + nt * 8 + 2 * t;
                    redc[c * 2 + wn] = c0v[nt];
                    redc[(c + 1) * 2 + wn] = c1v[nt];
                }
            }
        }
        __syncthreads();

        if (tid < 128) {
            float rv = fminf(fminf(redr[tid * 4], redr[tid * 4 + 1]),
                             fminf(redr[tid * 4 + 2], redr[tid * 4 + 3]));
            rv = fmaxf(rv, 0.0f);
            atomicMin((int*)&g_rowmin[(size_t)b * NN + n0 + tid], __float_as_int(rv));
        }
        if (colend) {
            float cv = fminf(redc[tid * 2], redc[tid * 2 + 1]);
            cv = fmaxf(cv, 0.0f);
            atomicMin((int*)&g_colmin[(size_t)b * MM + m0 + tid], __float_as_int(cv));
        }
        __syncthreads();
    }
}

// Weighted reduction; last block writes the output.
__global__ void partial_final_kernel(const float* __restrict__ w1,
                                     const float* __restrict__ w2,
                                     float* __restrict__ out) {
    __shared__ double sh[256];
    int tid = threadIdx.x;
    int gid = blockIdx.x * 256 + tid;
    int stride = gridDim.x * 256;
    double s = 0.0;
    for (int i = gid; i < BB * NN; i += stride)
        s += (double)w1[i] * sqrtf(g_rowmin[i]);
    for (int i = gid; i < BB * MM; i += stride)
        s += (double)w2[i] * sqrtf(g_colmin[i]);
    sh[tid] = s;
    __syncthreads();
    for (int off = 128; off > 0; off >>= 1) {
        if (tid < off) sh[tid] += sh[tid + off];
        __syncthreads();
    }
    if (tid == 0) {
        atomicAdd(&g_acc, sh[0]);
        __threadfence();
        int done = atomicAdd(&g_done, 1);
        if (done == (int)gridDim.x - 1) {
            double total = atomicAdd(&g_acc, 0.0);
            out[0] = (float)(total * 0.5);
            g_done = 0;
        }
    }
}

typedef CUresult (*EncodeFn)(CUtensorMap*, CUtensorMapDataType, cuuint32_t, void*,
                             const cuuint64_t*, const cuuint64_t*, const cuuint32_t*,
                             const cuuint32_t*, CUtensorMapInterleave, CUtensorMapSwizzle,
                             CUtensorMapL2promotion, CUtensorMapFloatOOBfill);

extern "C" void kernel_launch(void* const* d_in, const int* in_sizes, int n_in,
                              void* d_out, int out_size) {
    const float* set1 = (const float*)d_in[0];
    const float* set2 = (const float*)d_in[1];
    const float* w1   = (const float*)d_in[2];
    const float* w2   = (const float*)d_in[3];
    float* out = (float*)d_out;

    int nsm = 148;
    cudaDeviceGetAttribute(&nsm, cudaDevAttrMultiProcessorCount, 0);

    dim3 ngrid((BB * NN) / 8, 2, 1);
    convert_norms_kernel<<<ngrid, 256>>>(set1, set2);

    bool tma_ok = false;
    CUtensorMap tmX, tmY;
    {
        EncodeFn enc = nullptr;
        cudaDriverEntryPointQueryResult qr;
        if (cudaGetDriverEntryPoint("cuTensorMapEncodeTiled", (void**)&enc,
                                    cudaEnableDefault, &qr) == cudaSuccess && enc) {
            void *xaddr = nullptr, *yaddr = nullptr;
            cudaGetSymbolAddress(&xaddr, g_xh);
            cudaGetSymbolAddress(&yaddr, g_yh);
            if (xaddr && yaddr) {
                cuuint64_t dims[2] = {128, (cuuint64_t)BB * NN};
                cuuint64_t strides[1] = {CC * 2};
                cuuint32_t boxX[2] = {64, T2N}, boxY[2] = {64, T2M}, es[2] = {1, 1};
                CUresult r1 = enc(&tmX, CU_TENSOR_MAP_DATA_TYPE_UINT16, 2, xaddr,
                                  dims, strides, boxX, es,
                                  CU_TENSOR_MAP_INTERLEAVE_NONE, CU_TENSOR_MAP_SWIZZLE_128B,
                                  CU_TENSOR_MAP_L2_PROMOTION_L2_128B,
                                  CU_TENSOR_MAP_FLOAT_OOB_FILL_NONE);
                CUresult r2 = enc(&tmY, CU_TENSOR_MAP_DATA_TYPE_UINT16, 2, yaddr,
                                  dims, strides, boxY, es,
                                  CU_TENSOR_MAP_INTERLEAVE_NONE, CU_TENSOR_MAP_SWIZZLE_128B,
                                  CU_TENSOR_MAP_L2_PROMOTION_L2_128B,
                                  CU_TENSOR_MAP_FLOAT_OOB_FILL_NONE);
                tma_ok = (r1 == CUDA_SUCCESS) && (r2 == CUDA_SUCCESS);
            }
        }
    }

    if (tma_ok) {
        cudaFuncSetAttribute(chamfer_tma_kernel,
                             cudaFuncAttributeMaxDynamicSharedMemorySize, T2_SMEM);
        chamfer_tma_kernel<<<2 * nsm, 128, T2_SMEM>>>(tmX, tmY);
    } else {
        cudaFuncSetAttribute(chamfer_cp_kernel,
                             cudaFuncAttributeMaxDynamicSharedMemorySize, SMEM_BYTES);
        chamfer_cp_kernel<<<nsm, 256, SMEM_BYTES>>>();
    }

    partial_final_kernel<<<64, 256>>>(w1, w2, out);
}